// round 7
// baseline (speedup 1.0000x reference)
#include <cuda_runtime.h>
#include <math.h>

#define NN 50000
#define EE 800000

// ---------------- scratch ----------------
__device__ float g_qkv[NN * 384];     // [node][ q | k | v ]
__device__ float g_agg[NN * 128];
__device__ float g_eb [EE * 8];       // per-(edge,head) bias: ea @ We + be
__device__ int   g_cnt[NN];
__device__ int   g_off[NN + 1];
__device__ int2  g_list2[EE];         // {edge id, src node} grouped by dst

// ---------------- streams/events ----------------
static cudaStream_t s_side, s_side2;
static cudaEvent_t  s_evFork, s_evJoin, s_evJoin2;
static struct StreamInit {
    StreamInit() {
        cudaStreamCreateWithFlags(&s_side,  cudaStreamNonBlocking);
        cudaStreamCreateWithFlags(&s_side2, cudaStreamNonBlocking);
        cudaEventCreateWithFlags(&s_evFork,  cudaEventDisableTiming);
        cudaEventCreateWithFlags(&s_evJoin,  cudaEventDisableTiming);
        cudaEventCreateWithFlags(&s_evJoin2, cudaEventDisableTiming);
    }
} s_streamInit;

// ---------------- CSR build ----------------
__global__ void zero_cnt_k() {
    int i = blockIdx.x * blockDim.x + threadIdx.x;
    if (i < NN) g_cnt[i] = 0;
}

__global__ void hist_k(const int* __restrict__ ei) {
    int e = blockIdx.x * blockDim.x + threadIdx.x;
    if (e < EE) atomicAdd(&g_cnt[ei[EE + e]], 1);
}

__global__ __launch_bounds__(1024) void scan_k() {
    __shared__ int ssum[1024];
    const int T = 1024;
    const int CH = (NN + T - 1) / T;
    int t = threadIdx.x;
    int base = t * CH;

    int loc = 0;
    for (int i = 0; i < CH; i++) {
        int idx = base + i;
        if (idx < NN) loc += g_cnt[idx];
    }
    ssum[t] = loc;
    __syncthreads();
    for (int o = 1; o < T; o <<= 1) {
        int v = (t >= o) ? ssum[t - o] : 0;
        __syncthreads();
        ssum[t] += v;
        __syncthreads();
    }
    int run = (t == 0) ? 0 : ssum[t - 1];
    for (int i = 0; i < CH; i++) {
        int idx = base + i;
        if (idx < NN) {
            int c = g_cnt[idx];
            g_off[idx] = run;
            g_cnt[idx] = 0;
            run += c;
        }
    }
    if (t == T - 1) g_off[NN] = run;
}

__global__ void scatter_k(const int* __restrict__ ei) {
    int e = blockIdx.x * blockDim.x + threadIdx.x;
    if (e < EE) {
        int src = ei[e];
        int dst = ei[EE + e];
        int pos = atomicAdd(&g_cnt[dst], 1);
        g_list2[g_off[dst] + pos] = make_int2(e, src);
    }
}

// ---------------- edge-bias precompute, smem-staged (ea read exactly once) ----------------
// 256 threads / 32 edges per block. 25000 blocks (EE divisible by 32).
__global__ __launch_bounds__(256) void ebias_k(
    const float* __restrict__ ea, const float* __restrict__ We,
    const float* __restrict__ be)
{
    __shared__ float sWe[256];
    __shared__ float sbe[8];
    __shared__ float sea[32 * 32];
    const int t = threadIdx.x;
    sWe[t] = We[t];
    if (t < 8) sbe[t] = be[t];

    const size_t base = (size_t)blockIdx.x * 32 * 32;
#pragma unroll
    for (int i = 0; i < 4; i++)
        sea[i * 256 + t] = ea[base + i * 256 + t];
    __syncthreads();

    const int el = t >> 3;        // local edge 0..31
    const int h  = t & 7;
    const float* row = &sea[el * 32];
    float s = sbe[h];
#pragma unroll
    for (int c = 0; c < 32; c++)
        s += row[c] * sWe[c * 8 + h];
    g_eb[(size_t)blockIdx.x * 256 + t] = s;  // == (base_edge+el)*8 + h
}

// ---------------- TF32 helpers ----------------
__device__ __forceinline__ unsigned f2tf32(float f) {
    unsigned u;
    asm("cvt.rna.tf32.f32 %0, %1;" : "=r"(u) : "f"(f));
    return u;
}

__device__ __forceinline__ void mma_tf32(
    float& c0, float& c1, float& c2, float& c3,
    unsigned a0, unsigned a1, unsigned a2, unsigned a3,
    unsigned b0, unsigned b1)
{
    asm volatile(
        "mma.sync.aligned.m16n8k8.row.col.f32.tf32.tf32.f32 "
        "{%0,%1,%2,%3}, {%4,%5,%6,%7}, {%8,%9}, {%0,%1,%2,%3};"
        : "+f"(c0), "+f"(c1), "+f"(c2), "+f"(c3)
        : "r"(a0), "r"(a1), "r"(a2), "r"(a3), "r"(b0), "r"(b1));
}

#define BK 16

// ---------------- TF32 GEMM: QKV fused via blockIdx.y (weight select) ----------
__global__ __launch_bounds__(256) void gemm_qkv(
    const float* __restrict__ A,
    const float* __restrict__ Wq, const float* __restrict__ bq,
    const float* __restrict__ Wk, const float* __restrict__ bk,
    const float* __restrict__ Wv, const float* __restrict__ bv,
    float* __restrict__ C)
{
    const float* W    = (blockIdx.y == 0) ? Wq : (blockIdx.y == 1) ? Wk : Wv;
    const float* bias = (blockIdx.y == 0) ? bq : (blockIdx.y == 1) ? bk : bv;
    const int coloff  = blockIdx.y << 7;

    __shared__ unsigned As[2][BK][136];
    __shared__ unsigned Bs[2][BK][128];

    const int t    = threadIdx.x;
    const int wid  = t >> 5;
    const int lane = t & 31;
    const int wm   = wid & 1;
    const int wn   = wid >> 1;
    const int tig  = lane & 3;
    const int grp  = lane >> 2;
    const int rowBase = blockIdx.x * 128;

    float acc[4][4][4];
#pragma unroll
    for (int mi = 0; mi < 4; mi++)
#pragma unroll
        for (int ni = 0; ni < 4; ni++)
#pragma unroll
            for (int r = 0; r < 4; r++) acc[mi][ni][r] = 0.f;

    const int aRow0 = t >> 2;
    const int aC0   = (t & 3) << 2;
    const int aRow1 = (t + 256) >> 2;
    const int bK0 = t >> 5;
    const int bN0 = (t & 31) << 2;
    const int bK1 = bK0 + 8;

    const bool aOk0 = rowBase + aRow0 < NN;
    const bool aOk1 = rowBase + aRow1 < NN;
    const float* aP0 = A + (size_t)(rowBase + aRow0) * 128 + aC0;
    const float* aP1 = A + (size_t)(rowBase + aRow1) * 128 + aC0;

    float4 fa0 = make_float4(0.f,0.f,0.f,0.f), fa1 = fa0, fb0, fb1;
    if (aOk0) fa0 = *reinterpret_cast<const float4*>(aP0);
    if (aOk1) fa1 = *reinterpret_cast<const float4*>(aP1);
    fb0 = *reinterpret_cast<const float4*>(W + (size_t)bK0 * 128 + bN0);
    fb1 = *reinterpret_cast<const float4*>(W + (size_t)bK1 * 128 + bN0);

    int buf = 0;
    {
        As[0][aC0+0][aRow0] = f2tf32(fa0.x); As[0][aC0+1][aRow0] = f2tf32(fa0.y);
        As[0][aC0+2][aRow0] = f2tf32(fa0.z); As[0][aC0+3][aRow0] = f2tf32(fa0.w);
        As[0][aC0+0][aRow1] = f2tf32(fa1.x); As[0][aC0+1][aRow1] = f2tf32(fa1.y);
        As[0][aC0+2][aRow1] = f2tf32(fa1.z); As[0][aC0+3][aRow1] = f2tf32(fa1.w);
        Bs[0][bK0][bN0+0] = f2tf32(fb0.x); Bs[0][bK0][bN0+1] = f2tf32(fb0.y);
        Bs[0][bK0][bN0+2] = f2tf32(fb0.z); Bs[0][bK0][bN0+3] = f2tf32(fb0.w);
        Bs[0][bK1][bN0+0] = f2tf32(fb1.x); Bs[0][bK1][bN0+1] = f2tf32(fb1.y);
        Bs[0][bK1][bN0+2] = f2tf32(fb1.z); Bs[0][bK1][bN0+3] = f2tf32(fb1.w);
    }
    __syncthreads();

    for (int kb = 0; kb < 8; kb++) {
        const int nk = (kb + 1) * BK;
        if (kb < 7) {
            fa0 = make_float4(0.f,0.f,0.f,0.f); fa1 = fa0;
            if (aOk0) fa0 = *reinterpret_cast<const float4*>(aP0 + nk);
            if (aOk1) fa1 = *reinterpret_cast<const float4*>(aP1 + nk);
            fb0 = *reinterpret_cast<const float4*>(W + (size_t)(nk + bK0) * 128 + bN0);
            fb1 = *reinterpret_cast<const float4*>(W + (size_t)(nk + bK1) * 128 + bN0);
        }

#pragma unroll
        for (int ks = 0; ks < 2; ks++) {
            const int k0 = ks * 8;
            unsigned a[4][4];
#pragma unroll
            for (int mi = 0; mi < 4; mi++) {
                int mr = wm * 64 + mi * 16 + grp;
                a[mi][0] = As[buf][k0 + tig][mr];
                a[mi][1] = As[buf][k0 + tig][mr + 8];
                a[mi][2] = As[buf][k0 + tig + 4][mr];
                a[mi][3] = As[buf][k0 + tig + 4][mr + 8];
            }
            unsigned b[4][2];
#pragma unroll
            for (int ni = 0; ni < 4; ni++) {
                int nc = wn * 32 + ni * 8 + grp;
                b[ni][0] = Bs[buf][k0 + tig][nc];
                b[ni][1] = Bs[buf][k0 + tig + 4][nc];
            }
#pragma unroll
            for (int mi = 0; mi < 4; mi++)
#pragma unroll
                for (int ni = 0; ni < 4; ni++)
                    mma_tf32(acc[mi][ni][0], acc[mi][ni][1], acc[mi][ni][2], acc[mi][ni][3],
                             a[mi][0], a[mi][1], a[mi][2], a[mi][3],
                             b[ni][0], b[ni][1]);
        }

        if (kb < 7) {
            int nb = buf ^ 1;
            As[nb][aC0+0][aRow0] = f2tf32(fa0.x); As[nb][aC0+1][aRow0] = f2tf32(fa0.y);
            As[nb][aC0+2][aRow0] = f2tf32(fa0.z); As[nb][aC0+3][aRow0] = f2tf32(fa0.w);
            As[nb][aC0+0][aRow1] = f2tf32(fa1.x); As[nb][aC0+1][aRow1] = f2tf32(fa1.y);
            As[nb][aC0+2][aRow1] = f2tf32(fa1.z); As[nb][aC0+3][aRow1] = f2tf32(fa1.w);
            Bs[nb][bK0][bN0+0] = f2tf32(fb0.x); Bs[nb][bK0][bN0+1] = f2tf32(fb0.y);
            Bs[nb][bK0][bN0+2] = f2tf32(fb0.z); Bs[nb][bK0][bN0+3] = f2tf32(fb0.w);
            Bs[nb][bK1][bN0+0] = f2tf32(fb1.x); Bs[nb][bK1][bN0+1] = f2tf32(fb1.y);
            Bs[nb][bK1][bN0+2] = f2tf32(fb1.z); Bs[nb][bK1][bN0+3] = f2tf32(fb1.w);
            __syncthreads();
            buf = nb;
        }
    }

#pragma unroll
    for (int mi = 0; mi < 4; mi++) {
        int r0 = rowBase + wm * 64 + mi * 16 + grp;
        int r1 = r0 + 8;
#pragma unroll
        for (int ni = 0; ni < 4; ni++) {
            int c = wn * 32 + ni * 8 + tig * 2;
            float b0 = bias[c], b1 = bias[c + 1];
            if (r0 < NN) {
                float2 o = make_float2(acc[mi][ni][0] + b0, acc[mi][ni][1] + b1);
                *reinterpret_cast<float2*>(C + (size_t)r0 * 384 + coloff + c) = o;
            }
            if (r1 < NN) {
                float2 o = make_float2(acc[mi][ni][2] + b0, acc[mi][ni][3] + b1);
                *reinterpret_cast<float2*>(C + (size_t)r1 * 384 + coloff + c) = o;
            }
        }
    }
}

// ---------------- TF32 GEMM + fused LayerNorm (Wo variant) ----------
__global__ __launch_bounds__(256) void gemm_tf32_ln(
    const float* __restrict__ A, const float* __restrict__ W,
    const float* __restrict__ bias,
    const float* __restrict__ gamma, const float* __restrict__ beta,
    float* __restrict__ out)
{
    extern __shared__ char sm_[];
    typedef unsigned AsT[BK][136];
    typedef unsigned BsT[BK][128];
    AsT* As = reinterpret_cast<AsT*>(sm_);
    BsT* Bs = reinterpret_cast<BsT*>(sm_ + 17408);
    float (*Ct)[132] = reinterpret_cast<float(*)[132]>(sm_);

    const int t    = threadIdx.x;
    const int wid  = t >> 5;
    const int lane = t & 31;
    const int wm   = wid & 1;
    const int wn   = wid >> 1;
    const int tig  = lane & 3;
    const int grp  = lane >> 2;
    const int rowBase = blockIdx.x * 128;

    float acc[4][4][4];
#pragma unroll
    for (int mi = 0; mi < 4; mi++)
#pragma unroll
        for (int ni = 0; ni < 4; ni++)
#pragma unroll
            for (int r = 0; r < 4; r++) acc[mi][ni][r] = 0.f;

    const int aRow0 = t >> 2;
    const int aC0   = (t & 3) << 2;
    const int aRow1 = (t + 256) >> 2;
    const int bK0 = t >> 5;
    const int bN0 = (t & 31) << 2;
    const int bK1 = bK0 + 8;

    const bool aOk0 = rowBase + aRow0 < NN;
    const bool aOk1 = rowBase + aRow1 < NN;
    const float* aP0 = A + (size_t)(rowBase + aRow0) * 128 + aC0;
    const float* aP1 = A + (size_t)(rowBase + aRow1) * 128 + aC0;

    float4 fa0 = make_float4(0.f,0.f,0.f,0.f), fa1 = fa0, fb0, fb1;
    if (aOk0) fa0 = *reinterpret_cast<const float4*>(aP0);
    if (aOk1) fa1 = *reinterpret_cast<const float4*>(aP1);
    fb0 = *reinterpret_cast<const float4*>(W + (size_t)bK0 * 128 + bN0);
    fb1 = *reinterpret_cast<const float4*>(W + (size_t)bK1 * 128 + bN0);

    int buf = 0;
    {
        As[0][aC0+0][aRow0] = f2tf32(fa0.x); As[0][aC0+1][aRow0] = f2tf32(fa0.y);
        As[0][aC0+2][aRow0] = f2tf32(fa0.z); As[0][aC0+3][aRow0] = f2tf32(fa0.w);
        As[0][aC0+0][aRow1] = f2tf32(fa1.x); As[0][aC0+1][aRow1] = f2tf32(fa1.y);
        As[0][aC0+2][aRow1] = f2tf32(fa1.z); As[0][aC0+3][aRow1] = f2tf32(fa1.w);
        Bs[0][bK0][bN0+0] = f2tf32(fb0.x); Bs[0][bK0][bN0+1] = f2tf32(fb0.y);
        Bs[0][bK0][bN0+2] = f2tf32(fb0.z); Bs[0][bK0][bN0+3] = f2tf32(fb0.w);
        Bs[0][bK1][bN0+0] = f2tf32(fb1.x); Bs[0][bK1][bN0+1] = f2tf32(fb1.y);
        Bs[0][bK1][bN0+2] = f2tf32(fb1.z); Bs[0][bK1][bN0+3] = f2tf32(fb1.w);
    }
    __syncthreads();

    for (int kb = 0; kb < 8; kb++) {
        const int nk = (kb + 1) * BK;
        if (kb < 7) {
            fa0 = make_float4(0.f,0.f,0.f,0.f); fa1 = fa0;
            if (aOk0) fa0 = *reinterpret_cast<const float4*>(aP0 + nk);
            if (aOk1) fa1 = *reinterpret_cast<const float4*>(aP1 + nk);
            fb0 = *reinterpret_cast<const float4*>(W + (size_t)(nk + bK0) * 128 + bN0);
            fb1 = *reinterpret_cast<const float4*>(W + (size_t)(nk + bK1) * 128 + bN0);
        }

#pragma unroll
        for (int ks = 0; ks < 2; ks++) {
            const int k0 = ks * 8;
            unsigned a[4][4];
#pragma unroll
            for (int mi = 0; mi < 4; mi++) {
                int mr = wm * 64 + mi * 16 + grp;
                a[mi][0] = As[buf][k0 + tig][mr];
                a[mi][1] = As[buf][k0 + tig][mr + 8];
                a[mi][2] = As[buf][k0 + tig + 4][mr];
                a[mi][3] = As[buf][k0 + tig + 4][mr + 8];
            }
            unsigned b[4][2];
#pragma unroll
            for (int ni = 0; ni < 4; ni++) {
                int nc = wn * 32 + ni * 8 + grp;
                b[ni][0] = Bs[buf][k0 + tig][nc];
                b[ni][1] = Bs[buf][k0 + tig + 4][nc];
            }
#pragma unroll
            for (int mi = 0; mi < 4; mi++)
#pragma unroll
                for (int ni = 0; ni < 4; ni++)
                    mma_tf32(acc[mi][ni][0], acc[mi][ni][1], acc[mi][ni][2], acc[mi][ni][3],
                             a[mi][0], a[mi][1], a[mi][2], a[mi][3],
                             b[ni][0], b[ni][1]);
        }

        if (kb < 7) {
            int nb = buf ^ 1;
            As[nb][aC0+0][aRow0] = f2tf32(fa0.x); As[nb][aC0+1][aRow0] = f2tf32(fa0.y);
            As[nb][aC0+2][aRow0] = f2tf32(fa0.z); As[nb][aC0+3][aRow0] = f2tf32(fa0.w);
            As[nb][aC0+0][aRow1] = f2tf32(fa1.x); As[nb][aC0+1][aRow1] = f2tf32(fa1.y);
            As[nb][aC0+2][aRow1] = f2tf32(fa1.z); As[nb][aC0+3][aRow1] = f2tf32(fa1.w);
            Bs[nb][bK0][bN0+0] = f2tf32(fb0.x); Bs[nb][bK0][bN0+1] = f2tf32(fb0.y);
            Bs[nb][bK0][bN0+2] = f2tf32(fb0.z); Bs[nb][bK0][bN0+3] = f2tf32(fb0.w);
            Bs[nb][bK1][bN0+0] = f2tf32(fb1.x); Bs[nb][bK1][bN0+1] = f2tf32(fb1.y);
            Bs[nb][bK1][bN0+2] = f2tf32(fb1.z); Bs[nb][bK1][bN0+3] = f2tf32(fb1.w);
            __syncthreads();
            buf = nb;
        }
    }

    __syncthreads();
#pragma unroll
    for (int mi = 0; mi < 4; mi++) {
        int lr0 = wm * 64 + mi * 16 + grp;
        int lr1 = lr0 + 8;
#pragma unroll
        for (int ni = 0; ni < 4; ni++) {
            int c = wn * 32 + ni * 8 + tig * 2;
            float b0 = bias[c], b1 = bias[c + 1];
            Ct[lr0][c]     = acc[mi][ni][0] + b0;
            Ct[lr0][c + 1] = acc[mi][ni][1] + b1;
            Ct[lr1][c]     = acc[mi][ni][2] + b0;
            Ct[lr1][c + 1] = acc[mi][ni][3] + b1;
        }
    }
    __syncthreads();

    {
        int r = t >> 1;
        int half = (t & 1) << 6;
        int grow = rowBase + r;
        if (grow < NN) {
            float s = 0.f;
#pragma unroll
            for (int i = 0; i < 64; i += 4) {
                float4 v = *reinterpret_cast<float4*>(&Ct[r][half + i]);
                s += v.x + v.y + v.z + v.w;
            }
            s += __shfl_xor_sync(0xffffffffu, s, 1);
            float mean = s * (1.0f / 128.0f);

            float s2 = 0.f;
#pragma unroll
            for (int i = 0; i < 64; i += 4) {
                float4 v = *reinterpret_cast<float4*>(&Ct[r][half + i]);
                float dx = v.x - mean, dy = v.y - mean, dz = v.z - mean, dw = v.w - mean;
                s2 += dx * dx + dy * dy + dz * dz + dw * dw;
            }
            s2 += __shfl_xor_sync(0xffffffffu, s2, 1);
            float rstd = rsqrtf(s2 * (1.0f / 128.0f) + 1e-5f);

            float* op = out + (size_t)grow * 128 + half;
#pragma unroll
            for (int i = 0; i < 64; i += 4) {
                float4 v = *reinterpret_cast<float4*>(&Ct[r][half + i]);
                float4 gm = *reinterpret_cast<const float4*>(gamma + half + i);
                float4 bt = *reinterpret_cast<const float4*>(beta + half + i);
                float4 o;
                o.x = (v.x - mean) * rstd * gm.x + bt.x;
                o.y = (v.y - mean) * rstd * gm.y + bt.y;
                o.z = (v.z - mean) * rstd * gm.z + bt.z;
                o.w = (v.w - mean) * rstd * gm.w + bt.w;
                *reinterpret_cast<float4*>(op + i) = o;
            }
        } else {
            float s = 0.f;
            s += __shfl_xor_sync(0xffffffffu, s, 1);
            float s2 = 0.f;
            s2 += __shfl_xor_sync(0xffffffffu, s2, 1);
            (void)s; (void)s2;
        }
    }
}

// ---------------- fused attention: 4 warps per dst node, chunk-4, online softmax ----------------
// Block: 256 thr = 8 warps = 2 nodes x 4 quarter-warps.
__global__ __launch_bounds__(256) void attn_k(
    const float* __restrict__ qkv, float* __restrict__ agg)
{
    __shared__ float4 sAcc[8][32];
    __shared__ float  sM[8][33];
    __shared__ float  sD[8][33];

    const int warp = threadIdx.x >> 5;
    const int lane = threadIdx.x & 31;
    const int slot = warp >> 2;        // 0..1 node slot
    const int part = warp & 3;         // 0..3 quarter
    const int node = blockIdx.x * 2 + slot;
    const bool valid = node < NN;

    const int g = lane >> 2;

    int beg = 0, end = 0;
    if (valid) { beg = g_off[node]; end = g_off[node + 1]; }
    const int cnt = end - beg;
    const int b  = beg + (cnt * part) / 4;
    const int e_ = beg + (cnt * (part + 1)) / 4;

    float4 qv = make_float4(0.f, 0.f, 0.f, 0.f);
    if (valid && cnt > 0)
        qv = *reinterpret_cast<const float4*>(&qkv[(size_t)node * 384 + lane * 4]);

    const float NEG_INF = -__int_as_float(0x7F800000);
    float m = NEG_INF;
    float d = 0.f;
    float4 acc = make_float4(0.f, 0.f, 0.f, 0.f);

    int idx = b;
    for (; idx + 3 < e_; idx += 4) {
        int2 p0 = g_list2[idx];
        int2 p1 = g_list2[idx + 1];
        int2 p2 = g_list2[idx + 2];
        int2 p3 = g_list2[idx + 3];

        float4 k0 = *reinterpret_cast<const float4*>(&qkv[(size_t)p0.y * 384 + 128 + lane * 4]);
        float4 k1 = *reinterpret_cast<const float4*>(&qkv[(size_t)p1.y * 384 + 128 + lane * 4]);
        float4 k2 = *reinterpret_cast<const float4*>(&qkv[(size_t)p2.y * 384 + 128 + lane * 4]);
        float4 k3 = *reinterpret_cast<const float4*>(&qkv[(size_t)p3.y * 384 + 128 + lane * 4]);
        float4 v0 = *reinterpret_cast<const float4*>(&qkv[(size_t)p0.y * 384 + 256 + lane * 4]);
        float4 v1 = *reinterpret_cast<const float4*>(&qkv[(size_t)p1.y * 384 + 256 + lane * 4]);
        float4 v2 = *reinterpret_cast<const float4*>(&qkv[(size_t)p2.y * 384 + 256 + lane * 4]);
        float4 v3 = *reinterpret_cast<const float4*>(&qkv[(size_t)p3.y * 384 + 256 + lane * 4]);
        float eb0 = g_eb[(size_t)p0.x * 8 + g];
        float eb1 = g_eb[(size_t)p1.x * 8 + g];
        float eb2 = g_eb[(size_t)p2.x * 8 + g];
        float eb3 = g_eb[(size_t)p3.x * 8 + g];

        float t0 = qv.x*k0.x + qv.y*k0.y + qv.z*k0.z + qv.w*k0.w;
        float t1 = qv.x*k1.x + qv.y*k1.y + qv.z*k1.z + qv.w*k1.w;
        float t2 = qv.x*k2.x + qv.y*k2.y + qv.z*k2.z + qv.w*k2.w;
        float t3 = qv.x*k3.x + qv.y*k3.y + qv.z*k3.z + qv.w*k3.w;

        t0 += __shfl_xor_sync(0xffffffffu, t0, 1);
        t1 += __shfl_xor_sync(0xffffffffu, t1, 1);
        t2 += __shfl_xor_sync(0xffffffffu, t2, 1);
        t3 += __shfl_xor_sync(0xffffffffu, t3, 1);
        t0 += __shfl_xor_sync(0xffffffffu, t0, 2);
        t1 += __shfl_xor_sync(0xffffffffu, t1, 2);
        t2 += __shfl_xor_sync(0xffffffffu, t2, 2);
        t3 += __shfl_xor_sync(0xffffffffu, t3, 2);

        float sc0 = t0 * 0.25f + eb0;
        float sc1 = t1 * 0.25f + eb1;
        float sc2 = t2 * 0.25f + eb2;
        float sc3 = t3 * 0.25f + eb3;

        float mx = fmaxf(fmaxf(sc0, sc1), fmaxf(sc2, sc3));
        float mn = fmaxf(m, mx);
        float scale = __expf(m - mn);
        float q0 = __expf(sc0 - mn);
        float q1 = __expf(sc1 - mn);
        float q2 = __expf(sc2 - mn);
        float q3 = __expf(sc3 - mn);
        d = d * scale + q0 + q1 + q2 + q3;
        acc.x = acc.x * scale + q0*v0.x + q1*v1.x + q2*v2.x + q3*v3.x;
        acc.y = acc.y * scale + q0*v0.y + q1*v1.y + q2*v2.y + q3*v3.y;
        acc.z = acc.z * scale + q0*v0.z + q1*v1.z + q2*v2.z + q3*v3.z;
        acc.w = acc.w * scale + q0*v0.w + q1*v1.w + q2*v2.w + q3*v3.w;
        m = mn;
    }

    for (; idx < e_; idx++) {
        int2 p = g_list2[idx];
        float4 kv = *reinterpret_cast<const float4*>(&qkv[(size_t)p.y * 384 + 128 + lane * 4]);
        float4 vv = *reinterpret_cast<const float4*>(&qkv[(size_t)p.y * 384 + 256 + lane * 4]);
        float eb = g_eb[(size_t)p.x * 8 + g];

        float s = qv.x*kv.x + qv.y*kv.y + qv.z*kv.z + qv.w*kv.w;
        s += __shfl_xor_sync(0xffffffffu, s, 1);
        s += __shfl_xor_sync(0xffffffffu, s, 2);
        s = s * 0.25f + eb;

        float mn = fmaxf(m, s);
        float scale = __expf(m - mn);
        float p_ = __expf(s - mn);
        d = d * scale + p_;
        acc.x = acc.x * scale + p_ * vv.x;
        acc.y = acc.y * scale + p_ * vv.y;
        acc.z = acc.z * scale + p_ * vv.z;
        acc.w = acc.w * scale + p_ * vv.w;
        m = mn;
    }

    sM[warp][lane] = m;
    sD[warp][lane] = d;
    sAcc[warp][lane] = acc;
    __syncthreads();

    if (part == 0 && valid) {
        float* op = &agg[(size_t)node * 128 + lane * 4];
        if (cnt == 0) {
            *reinterpret_cast<float4*>(op) = make_float4(0.f, 0.f, 0.f, 0.f);
        } else {
            float m1 = sM[warp + 1][lane];
            float m2 = sM[warp + 2][lane];
            float m3 = sM[warp + 3][lane];
            float mn = fmaxf(fmaxf(m, m1), fmaxf(m2, m3));

            float s0 = (m  == NEG_INF) ? 0.f : __expf(m  - mn);
            float s1 = (m1 == NEG_INF) ? 0.f : __expf(m1 - mn);
            float s2 = (m2 == NEG_INF) ? 0.f : __expf(m2 - mn);
            float s3 = (m3 == NEG_INF) ? 0.f : __expf(m3 - mn);

            float dt = d * s0 + sD[warp + 1][lane] * s1
                     + sD[warp + 2][lane] * s2 + sD[warp + 3][lane] * s3;
            float4 a1 = sAcc[warp + 1][lane];
            float4 a2 = sAcc[warp + 2][lane];
            float4 a3 = sAcc[warp + 3][lane];

            float inv = 1.0f / dt;
            float4 o;
            o.x = (acc.x * s0 + a1.x * s1 + a2.x * s2 + a3.x * s3) * inv;
            o.y = (acc.y * s0 + a1.y * s1 + a2.y * s2 + a3.y * s3) * inv;
            o.z = (acc.z * s0 + a1.z * s1 + a2.z * s2 + a3.z * s3) * inv;
            o.w = (acc.w * s0 + a1.w * s1 + a2.w * s2 + a3.w * s3) * inv;
            *reinterpret_cast<float4*>(op) = o;
        }
    }
}

// ---------------- launch ----------------
extern "C" void kernel_launch(void* const* d_in, const int* in_sizes, int n_in,
                              void* d_out, int out_size)
{
    const float* x     = (const float*)d_in[0];
    const float* ea    = (const float*)d_in[1];
    const float* Wq    = (const float*)d_in[2];
    const float* bq    = (const float*)d_in[3];
    const float* Wk    = (const float*)d_in[4];
    const float* bk    = (const float*)d_in[5];
    const float* Wv    = (const float*)d_in[6];
    const float* bv    = (const float*)d_in[7];
    const float* We    = (const float*)d_in[8];
    const float* be    = (const float*)d_in[9];
    const float* Wo    = (const float*)d_in[10];
    const float* bo    = (const float*)d_in[11];
    const float* gamma = (const float*)d_in[12];
    const float* beta  = (const float*)d_in[13];
    const int*   ei    = (const int*)d_in[14];
    float* out = (float*)d_out;

    float *qkv, *agg;
    cudaGetSymbolAddress((void**)&qkv, g_qkv);
    cudaGetSymbolAddress((void**)&agg, g_agg);

    static bool attrSet = false;
    if (!attrSet) {
        cudaFuncSetAttribute(gemm_tf32_ln,
                             cudaFuncAttributeMaxDynamicSharedMemorySize, 69632);
        attrSet = true;
    }

    const int nTiles = (NN + 127) / 128;
    const size_t lnSmem = 128 * 132 * 4;

    cudaEventRecord(s_evFork, 0);
    cudaStreamWaitEvent(s_side,  s_evFork, 0);
    cudaStreamWaitEvent(s_side2, s_evFork, 0);

    // side stream 1: CSR
    zero_cnt_k<<<(NN + 255) / 256, 256, 0, s_side>>>();
    hist_k<<<(EE + 255) / 256, 256, 0, s_side>>>(ei);
    scan_k<<<1, 1024, 0, s_side>>>();
    scatter_k<<<(EE + 255) / 256, 256, 0, s_side>>>(ei);
    cudaEventRecord(s_evJoin, s_side);

    // side stream 2: edge bias (ea read once via smem staging)
    ebias_k<<<EE / 32, 256, 0, s_side2>>>(ea, We, be);
    cudaEventRecord(s_evJoin2, s_side2);

    // main stream: fused QKV GEMM (single launch, 3 weight sets)
    gemm_qkv<<<dim3(nTiles, 3), 256>>>(x, Wq, bq, Wk, bk, Wv, bv, qkv);

    cudaStreamWaitEvent(0, s_evJoin, 0);
    cudaStreamWaitEvent(0, s_evJoin2, 0);

    attn_k<<<(NN + 1) / 2, 256>>>(qkv, agg);

    gemm_tf32_ln<<<nTiles, 256, lnSmem>>>(agg, Wo, bo, gamma, beta, out);
}

// round 8
// speedup vs baseline: 1.2519x; 1.2519x over previous
#include <cuda_runtime.h>
#include <math.h>

#define NN 50000
#define EE 800000

// ---------------- scratch ----------------
__device__ float g_qkv[NN * 384];     // [node][ q | k | v ]
__device__ float g_agg[NN * 128];
__device__ float g_eb [EE * 8];       // per-(edge,head) bias: ea @ We + be
__device__ int   g_cnt[NN];
__device__ int   g_off[NN + 1];
__device__ int2  g_list2[EE];         // {edge id, src node} grouped by dst

// ---------------- streams/events ----------------
static cudaStream_t s_side, s_side2;
static cudaEvent_t  s_evFork, s_evJoin, s_evJoin2, s_evA, s_evLnA;
static struct StreamInit {
    StreamInit() {
        cudaStreamCreateWithFlags(&s_side,  cudaStreamNonBlocking);
        cudaStreamCreateWithFlags(&s_side2, cudaStreamNonBlocking);
        cudaEventCreateWithFlags(&s_evFork,  cudaEventDisableTiming);
        cudaEventCreateWithFlags(&s_evJoin,  cudaEventDisableTiming);
        cudaEventCreateWithFlags(&s_evJoin2, cudaEventDisableTiming);
        cudaEventCreateWithFlags(&s_evA,     cudaEventDisableTiming);
        cudaEventCreateWithFlags(&s_evLnA,   cudaEventDisableTiming);
    }
} s_streamInit;

// ---------------- CSR build ----------------
__global__ void zero_cnt_k() {
    int i = blockIdx.x * blockDim.x + threadIdx.x;
    if (i < NN) g_cnt[i] = 0;
}

__global__ void hist_k(const int* __restrict__ ei) {
    int e = blockIdx.x * blockDim.x + threadIdx.x;
    if (e < EE) atomicAdd(&g_cnt[ei[EE + e]], 1);
}

__global__ __launch_bounds__(1024) void scan_k() {
    __shared__ int ssum[1024];
    const int T = 1024;
    const int CH = (NN + T - 1) / T;
    int t = threadIdx.x;
    int base = t * CH;

    int loc = 0;
    for (int i = 0; i < CH; i++) {
        int idx = base + i;
        if (idx < NN) loc += g_cnt[idx];
    }
    ssum[t] = loc;
    __syncthreads();
    for (int o = 1; o < T; o <<= 1) {
        int v = (t >= o) ? ssum[t - o] : 0;
        __syncthreads();
        ssum[t] += v;
        __syncthreads();
    }
    int run = (t == 0) ? 0 : ssum[t - 1];
    for (int i = 0; i < CH; i++) {
        int idx = base + i;
        if (idx < NN) {
            int c = g_cnt[idx];
            g_off[idx] = run;
            g_cnt[idx] = 0;
            run += c;
        }
    }
    if (t == T - 1) g_off[NN] = run;
}

__global__ void scatter_k(const int* __restrict__ ei) {
    int e = blockIdx.x * blockDim.x + threadIdx.x;
    if (e < EE) {
        int src = ei[e];
        int dst = ei[EE + e];
        int pos = atomicAdd(&g_cnt[dst], 1);
        g_list2[g_off[dst] + pos] = make_int2(e, src);
    }
}

// ---------------- edge-bias precompute (R6 version) ----------------
__global__ __launch_bounds__(256) void ebias_k(
    const float* __restrict__ ea, const float* __restrict__ We,
    const float* __restrict__ be)
{
    __shared__ float sWe[256];
    __shared__ float sbe[8];
    int t = threadIdx.x;
    sWe[t] = We[t];
    if (t < 8) sbe[t] = be[t];
    __syncthreads();

    int gid = blockIdx.x * 256 + t;
    if (gid >= EE * 8) return;
    int e = gid >> 3, h = gid & 7;

    float s = sbe[h];
    const float4* ep = reinterpret_cast<const float4*>(ea + (size_t)e * 32);
#pragma unroll
    for (int i = 0; i < 8; i++) {
        float4 v = ep[i];
        s += v.x * sWe[(i * 4 + 0) * 8 + h] + v.y * sWe[(i * 4 + 1) * 8 + h]
           + v.z * sWe[(i * 4 + 2) * 8 + h] + v.w * sWe[(i * 4 + 3) * 8 + h];
    }
    g_eb[gid] = s;
}

// ---------------- TF32 helpers ----------------
__device__ __forceinline__ unsigned f2tf32(float f) {
    unsigned u;
    asm("cvt.rna.tf32.f32 %0, %1;" : "=r"(u) : "f"(f));
    return u;
}

__device__ __forceinline__ void mma_tf32(
    float& c0, float& c1, float& c2, float& c3,
    unsigned a0, unsigned a1, unsigned a2, unsigned a3,
    unsigned b0, unsigned b1)
{
    asm volatile(
        "mma.sync.aligned.m16n8k8.row.col.f32.tf32.tf32.f32 "
        "{%0,%1,%2,%3}, {%4,%5,%6,%7}, {%8,%9}, {%0,%1,%2,%3};"
        : "+f"(c0), "+f"(c1), "+f"(c2), "+f"(c3)
        : "r"(a0), "r"(a1), "r"(a2), "r"(a3), "r"(b0), "r"(b1));
}

#define BK 16

// ---------------- TF32 GEMM [N,128]x[128,128]+bias (QKV variant) ----------
__global__ __launch_bounds__(256) void gemm_tf32(
    const float* __restrict__ A, const float* __restrict__ W,
    const float* __restrict__ bias, float* __restrict__ C,
    int ldc, int coloff)
{
    __shared__ unsigned As[2][BK][136];
    __shared__ unsigned Bs[2][BK][128];

    const int t    = threadIdx.x;
    const int wid  = t >> 5;
    const int lane = t & 31;
    const int wm   = wid & 1;
    const int wn   = wid >> 1;
    const int tig  = lane & 3;
    const int grp  = lane >> 2;
    const int rowBase = blockIdx.x * 128;

    float acc[4][4][4];
#pragma unroll
    for (int mi = 0; mi < 4; mi++)
#pragma unroll
        for (int ni = 0; ni < 4; ni++)
#pragma unroll
            for (int r = 0; r < 4; r++) acc[mi][ni][r] = 0.f;

    const int aRow0 = t >> 2;
    const int aC0   = (t & 3) << 2;
    const int aRow1 = (t + 256) >> 2;
    const int bK0 = t >> 5;
    const int bN0 = (t & 31) << 2;
    const int bK1 = bK0 + 8;

    const bool aOk0 = rowBase + aRow0 < NN;
    const bool aOk1 = rowBase + aRow1 < NN;
    const float* aP0 = A + (size_t)(rowBase + aRow0) * 128 + aC0;
    const float* aP1 = A + (size_t)(rowBase + aRow1) * 128 + aC0;

    float4 fa0 = make_float4(0.f,0.f,0.f,0.f), fa1 = fa0, fb0, fb1;
    if (aOk0) fa0 = *reinterpret_cast<const float4*>(aP0);
    if (aOk1) fa1 = *reinterpret_cast<const float4*>(aP1);
    fb0 = *reinterpret_cast<const float4*>(W + (size_t)bK0 * 128 + bN0);
    fb1 = *reinterpret_cast<const float4*>(W + (size_t)bK1 * 128 + bN0);

    int buf = 0;
    {
        As[0][aC0+0][aRow0] = f2tf32(fa0.x); As[0][aC0+1][aRow0] = f2tf32(fa0.y);
        As[0][aC0+2][aRow0] = f2tf32(fa0.z); As[0][aC0+3][aRow0] = f2tf32(fa0.w);
        As[0][aC0+0][aRow1] = f2tf32(fa1.x); As[0][aC0+1][aRow1] = f2tf32(fa1.y);
        As[0][aC0+2][aRow1] = f2tf32(fa1.z); As[0][aC0+3][aRow1] = f2tf32(fa1.w);
        Bs[0][bK0][bN0+0] = f2tf32(fb0.x); Bs[0][bK0][bN0+1] = f2tf32(fb0.y);
        Bs[0][bK0][bN0+2] = f2tf32(fb0.z); Bs[0][bK0][bN0+3] = f2tf32(fb0.w);
        Bs[0][bK1][bN0+0] = f2tf32(fb1.x); Bs[0][bK1][bN0+1] = f2tf32(fb1.y);
        Bs[0][bK1][bN0+2] = f2tf32(fb1.z); Bs[0][bK1][bN0+3] = f2tf32(fb1.w);
    }
    __syncthreads();

    for (int kb = 0; kb < 8; kb++) {
        const int nk = (kb + 1) * BK;
        if (kb < 7) {
            fa0 = make_float4(0.f,0.f,0.f,0.f); fa1 = fa0;
            if (aOk0) fa0 = *reinterpret_cast<const float4*>(aP0 + nk);
            if (aOk1) fa1 = *reinterpret_cast<const float4*>(aP1 + nk);
            fb0 = *reinterpret_cast<const float4*>(W + (size_t)(nk + bK0) * 128 + bN0);
            fb1 = *reinterpret_cast<const float4*>(W + (size_t)(nk + bK1) * 128 + bN0);
        }

#pragma unroll
        for (int ks = 0; ks < 2; ks++) {
            const int k0 = ks * 8;
            unsigned a[4][4];
#pragma unroll
            for (int mi = 0; mi < 4; mi++) {
                int mr = wm * 64 + mi * 16 + grp;
                a[mi][0] = As[buf][k0 + tig][mr];
                a[mi][1] = As[buf][k0 + tig][mr + 8];
                a[mi][2] = As[buf][k0 + tig + 4][mr];
                a[mi][3] = As[buf][k0 + tig + 4][mr + 8];
            }
            unsigned b[4][2];
#pragma unroll
            for (int ni = 0; ni < 4; ni++) {
                int nc = wn * 32 + ni * 8 + grp;
                b[ni][0] = Bs[buf][k0 + tig][nc];
                b[ni][1] = Bs[buf][k0 + tig + 4][nc];
            }
#pragma unroll
            for (int mi = 0; mi < 4; mi++)
#pragma unroll
                for (int ni = 0; ni < 4; ni++)
                    mma_tf32(acc[mi][ni][0], acc[mi][ni][1], acc[mi][ni][2], acc[mi][ni][3],
                             a[mi][0], a[mi][1], a[mi][2], a[mi][3],
                             b[ni][0], b[ni][1]);
        }

        if (kb < 7) {
            int nb = buf ^ 1;
            As[nb][aC0+0][aRow0] = f2tf32(fa0.x); As[nb][aC0+1][aRow0] = f2tf32(fa0.y);
            As[nb][aC0+2][aRow0] = f2tf32(fa0.z); As[nb][aC0+3][aRow0] = f2tf32(fa0.w);
            As[nb][aC0+0][aRow1] = f2tf32(fa1.x); As[nb][aC0+1][aRow1] = f2tf32(fa1.y);
            As[nb][aC0+2][aRow1] = f2tf32(fa1.z); As[nb][aC0+3][aRow1] = f2tf32(fa1.w);
            Bs[nb][bK0][bN0+0] = f2tf32(fb0.x); Bs[nb][bK0][bN0+1] = f2tf32(fb0.y);
            Bs[nb][bK0][bN0+2] = f2tf32(fb0.z); Bs[nb][bK0][bN0+3] = f2tf32(fb0.w);
            Bs[nb][bK1][bN0+0] = f2tf32(fb1.x); Bs[nb][bK1][bN0+1] = f2tf32(fb1.y);
            Bs[nb][bK1][bN0+2] = f2tf32(fb1.z); Bs[nb][bK1][bN0+3] = f2tf32(fb1.w);
            __syncthreads();
            buf = nb;
        }
    }

#pragma unroll
    for (int mi = 0; mi < 4; mi++) {
        int r0 = rowBase + wm * 64 + mi * 16 + grp;
        int r1 = r0 + 8;
#pragma unroll
        for (int ni = 0; ni < 4; ni++) {
            int c = wn * 32 + ni * 8 + tig * 2;
            float b0 = bias[c], b1 = bias[c + 1];
            if (r0 < NN) {
                float2 o = make_float2(acc[mi][ni][0] + b0, acc[mi][ni][1] + b1);
                *reinterpret_cast<float2*>(C + (size_t)r0 * ldc + coloff + c) = o;
            }
            if (r1 < NN) {
                float2 o = make_float2(acc[mi][ni][2] + b0, acc[mi][ni][3] + b1);
                *reinterpret_cast<float2*>(C + (size_t)r1 * ldc + coloff + c) = o;
            }
        }
    }
}

// ---------------- TF32 GEMM + fused LayerNorm (Wo variant, tile-range) ----------
__global__ __launch_bounds__(256) void gemm_tf32_ln(
    const float* __restrict__ A, const float* __restrict__ W,
    const float* __restrict__ bias,
    const float* __restrict__ gamma, const float* __restrict__ beta,
    float* __restrict__ out, int tileOff)
{
    extern __shared__ char sm_[];
    typedef unsigned AsT[BK][136];
    typedef unsigned BsT[BK][128];
    AsT* As = reinterpret_cast<AsT*>(sm_);
    BsT* Bs = reinterpret_cast<BsT*>(sm_ + 17408);
    float (*Ct)[132] = reinterpret_cast<float(*)[132]>(sm_);

    const int t    = threadIdx.x;
    const int wid  = t >> 5;
    const int lane = t & 31;
    const int wm   = wid & 1;
    const int wn   = wid >> 1;
    const int tig  = lane & 3;
    const int grp  = lane >> 2;
    const int rowBase = (tileOff + blockIdx.x) * 128;

    float acc[4][4][4];
#pragma unroll
    for (int mi = 0; mi < 4; mi++)
#pragma unroll
        for (int ni = 0; ni < 4; ni++)
#pragma unroll
            for (int r = 0; r < 4; r++) acc[mi][ni][r] = 0.f;

    const int aRow0 = t >> 2;
    const int aC0   = (t & 3) << 2;
    const int aRow1 = (t + 256) >> 2;
    const int bK0 = t >> 5;
    const int bN0 = (t & 31) << 2;
    const int bK1 = bK0 + 8;

    const bool aOk0 = rowBase + aRow0 < NN;
    const bool aOk1 = rowBase + aRow1 < NN;
    const float* aP0 = A + (size_t)(rowBase + aRow0) * 128 + aC0;
    const float* aP1 = A + (size_t)(rowBase + aRow1) * 128 + aC0;

    float4 fa0 = make_float4(0.f,0.f,0.f,0.f), fa1 = fa0, fb0, fb1;
    if (aOk0) fa0 = *reinterpret_cast<const float4*>(aP0);
    if (aOk1) fa1 = *reinterpret_cast<const float4*>(aP1);
    fb0 = *reinterpret_cast<const float4*>(W + (size_t)bK0 * 128 + bN0);
    fb1 = *reinterpret_cast<const float4*>(W + (size_t)bK1 * 128 + bN0);

    int buf = 0;
    {
        As[0][aC0+0][aRow0] = f2tf32(fa0.x); As[0][aC0+1][aRow0] = f2tf32(fa0.y);
        As[0][aC0+2][aRow0] = f2tf32(fa0.z); As[0][aC0+3][aRow0] = f2tf32(fa0.w);
        As[0][aC0+0][aRow1] = f2tf32(fa1.x); As[0][aC0+1][aRow1] = f2tf32(fa1.y);
        As[0][aC0+2][aRow1] = f2tf32(fa1.z); As[0][aC0+3][aRow1] = f2tf32(fa1.w);
        Bs[0][bK0][bN0+0] = f2tf32(fb0.x); Bs[0][bK0][bN0+1] = f2tf32(fb0.y);
        Bs[0][bK0][bN0+2] = f2tf32(fb0.z); Bs[0][bK0][bN0+3] = f2tf32(fb0.w);
        Bs[0][bK1][bN0+0] = f2tf32(fb1.x); Bs[0][bK1][bN0+1] = f2tf32(fb1.y);
        Bs[0][bK1][bN0+2] = f2tf32(fb1.z); Bs[0][bK1][bN0+3] = f2tf32(fb1.w);
    }
    __syncthreads();

    for (int kb = 0; kb < 8; kb++) {
        const int nk = (kb + 1) * BK;
        if (kb < 7) {
            fa0 = make_float4(0.f,0.f,0.f,0.f); fa1 = fa0;
            if (aOk0) fa0 = *reinterpret_cast<const float4*>(aP0 + nk);
            if (aOk1) fa1 = *reinterpret_cast<const float4*>(aP1 + nk);
            fb0 = *reinterpret_cast<const float4*>(W + (size_t)(nk + bK0) * 128 + bN0);
            fb1 = *reinterpret_cast<const float4*>(W + (size_t)(nk + bK1) * 128 + bN0);
        }

#pragma unroll
        for (int ks = 0; ks < 2; ks++) {
            const int k0 = ks * 8;
            unsigned a[4][4];
#pragma unroll
            for (int mi = 0; mi < 4; mi++) {
                int mr = wm * 64 + mi * 16 + grp;
                a[mi][0] = As[buf][k0 + tig][mr];
                a[mi][1] = As[buf][k0 + tig][mr + 8];
                a[mi][2] = As[buf][k0 + tig + 4][mr];
                a[mi][3] = As[buf][k0 + tig + 4][mr + 8];
            }
            unsigned b[4][2];
#pragma unroll
            for (int ni = 0; ni < 4; ni++) {
                int nc = wn * 32 + ni * 8 + grp;
                b[ni][0] = Bs[buf][k0 + tig][nc];
                b[ni][1] = Bs[buf][k0 + tig + 4][nc];
            }
#pragma unroll
            for (int mi = 0; mi < 4; mi++)
#pragma unroll
                for (int ni = 0; ni < 4; ni++)
                    mma_tf32(acc[mi][ni][0], acc[mi][ni][1], acc[mi][ni][2], acc[mi][ni][3],
                             a[mi][0], a[mi][1], a[mi][2], a[mi][3],
                             b[ni][0], b[ni][1]);
        }

        if (kb < 7) {
            int nb = buf ^ 1;
            As[nb][aC0+0][aRow0] = f2tf32(fa0.x); As[nb][aC0+1][aRow0] = f2tf32(fa0.y);
            As[nb][aC0+2][aRow0] = f2tf32(fa0.z); As[nb][aC0+3][aRow0] = f2tf32(fa0.w);
            As[nb][aC0+0][aRow1] = f2tf32(fa1.x); As[nb][aC0+1][aRow1] = f2tf32(fa1.y);
            As[nb][aC0+2][aRow1] = f2tf32(fa1.z); As[nb][aC0+3][aRow1] = f2tf32(fa1.w);
            Bs[nb][bK0][bN0+0] = f2tf32(fb0.x); Bs[nb][bK0][bN0+1] = f2tf32(fb0.y);
            Bs[nb][bK0][bN0+2] = f2tf32(fb0.z); Bs[nb][bK0][bN0+3] = f2tf32(fb0.w);
            Bs[nb][bK1][bN0+0] = f2tf32(fb1.x); Bs[nb][bK1][bN0+1] = f2tf32(fb1.y);
            Bs[nb][bK1][bN0+2] = f2tf32(fb1.z); Bs[nb][bK1][bN0+3] = f2tf32(fb1.w);
            __syncthreads();
            buf = nb;
        }
    }

    __syncthreads();
#pragma unroll
    for (int mi = 0; mi < 4; mi++) {
        int lr0 = wm * 64 + mi * 16 + grp;
        int lr1 = lr0 + 8;
#pragma unroll
        for (int ni = 0; ni < 4; ni++) {
            int c = wn * 32 + ni * 8 + tig * 2;
            float b0 = bias[c], b1 = bias[c + 1];
            Ct[lr0][c]     = acc[mi][ni][0] + b0;
            Ct[lr0][c + 1] = acc[mi][ni][1] + b1;
            Ct[lr1][c]     = acc[mi][ni][2] + b0;
            Ct[lr1][c + 1] = acc[mi][ni][3] + b1;
        }
    }
    __syncthreads();

    {
        int r = t >> 1;
        int half = (t & 1) << 6;
        int grow = rowBase + r;
        if (grow < NN) {
            float s = 0.f;
#pragma unroll
            for (int i = 0; i < 64; i += 4) {
                float4 v = *reinterpret_cast<float4*>(&Ct[r][half + i]);
                s += v.x + v.y + v.z + v.w;
            }
            s += __shfl_xor_sync(0xffffffffu, s, 1);
            float mean = s * (1.0f / 128.0f);

            float s2 = 0.f;
#pragma unroll
            for (int i = 0; i < 64; i += 4) {
                float4 v = *reinterpret_cast<float4*>(&Ct[r][half + i]);
                float dx = v.x - mean, dy = v.y - mean, dz = v.z - mean, dw = v.w - mean;
                s2 += dx * dx + dy * dy + dz * dz + dw * dw;
            }
            s2 += __shfl_xor_sync(0xffffffffu, s2, 1);
            float rstd = rsqrtf(s2 * (1.0f / 128.0f) + 1e-5f);

            float* op = out + (size_t)grow * 128 + half;
#pragma unroll
            for (int i = 0; i < 64; i += 4) {
                float4 v = *reinterpret_cast<float4*>(&Ct[r][half + i]);
                float4 gm = *reinterpret_cast<const float4*>(gamma + half + i);
                float4 bt = *reinterpret_cast<const float4*>(beta + half + i);
                float4 o;
                o.x = (v.x - mean) * rstd * gm.x + bt.x;
                o.y = (v.y - mean) * rstd * gm.y + bt.y;
                o.z = (v.z - mean) * rstd * gm.z + bt.z;
                o.w = (v.w - mean) * rstd * gm.w + bt.w;
                *reinterpret_cast<float4*>(op + i) = o;
            }
        } else {
            float s = 0.f;
            s += __shfl_xor_sync(0xffffffffu, s, 1);
            float s2 = 0.f;
            s2 += __shfl_xor_sync(0xffffffffu, s2, 1);
            (void)s; (void)s2;
        }
    }
}

// ---------------- fused attention (R6 version): 2 warps/node, chunk-4, node-range ----------------
__global__ __launch_bounds__(256) void attn_k(
    const float* __restrict__ qkv, float* __restrict__ agg, int nodeBase)
{
    __shared__ float4 sAcc[8][32];
    __shared__ float  sM[8][33];
    __shared__ float  sD[8][33];

    const int warp = threadIdx.x >> 5;
    const int lane = threadIdx.x & 31;
    const int slot = warp >> 1;
    const int half = warp & 1;
    const int node = nodeBase + blockIdx.x * 4 + slot;
    const bool valid = node < NN;

    const int g = lane >> 2;

    int beg = 0, end = 0;
    if (valid) { beg = g_off[node]; end = g_off[node + 1]; }
    const int cnt = end - beg;
    const int h0 = (cnt + 1) >> 1;
    const int b  = half ? (beg + h0) : beg;
    const int e_ = half ? end : (beg + h0);

    float4 qv = make_float4(0.f, 0.f, 0.f, 0.f);
    if (valid && cnt > 0)
        qv = *reinterpret_cast<const float4*>(&qkv[(size_t)node * 384 + lane * 4]);

    const float NEG_INF = -__int_as_float(0x7F800000);
    float m = NEG_INF;
    float d = 0.f;
    float4 acc = make_float4(0.f, 0.f, 0.f, 0.f);

    int idx = b;
    for (; idx + 3 < e_; idx += 4) {
        int2 p0 = g_list2[idx];
        int2 p1 = g_list2[idx + 1];
        int2 p2 = g_list2[idx + 2];
        int2 p3 = g_list2[idx + 3];

        float4 k0 = *reinterpret_cast<const float4*>(&qkv[(size_t)p0.y * 384 + 128 + lane * 4]);
        float4 k1 = *reinterpret_cast<const float4*>(&qkv[(size_t)p1.y * 384 + 128 + lane * 4]);
        float4 k2 = *reinterpret_cast<const float4*>(&qkv[(size_t)p2.y * 384 + 128 + lane * 4]);
        float4 k3 = *reinterpret_cast<const float4*>(&qkv[(size_t)p3.y * 384 + 128 + lane * 4]);
        float4 v0 = *reinterpret_cast<const float4*>(&qkv[(size_t)p0.y * 384 + 256 + lane * 4]);
        float4 v1 = *reinterpret_cast<const float4*>(&qkv[(size_t)p1.y * 384 + 256 + lane * 4]);
        float4 v2 = *reinterpret_cast<const float4*>(&qkv[(size_t)p2.y * 384 + 256 + lane * 4]);
        float4 v3 = *reinterpret_cast<const float4*>(&qkv[(size_t)p3.y * 384 + 256 + lane * 4]);
        float eb0 = g_eb[(size_t)p0.x * 8 + g];
        float eb1 = g_eb[(size_t)p1.x * 8 + g];
        float eb2 = g_eb[(size_t)p2.x * 8 + g];
        float eb3 = g_eb[(size_t)p3.x * 8 + g];

        float t0 = qv.x*k0.x + qv.y*k0.y + qv.z*k0.z + qv.w*k0.w;
        float t1 = qv.x*k1.x + qv.y*k1.y + qv.z*k1.z + qv.w*k1.w;
        float t2 = qv.x*k2.x + qv.y*k2.y + qv.z*k2.z + qv.w*k2.w;
        float t3 = qv.x*k3.x + qv.y*k3.y + qv.z*k3.z + qv.w*k3.w;

        t0 += __shfl_xor_sync(0xffffffffu, t0, 1);
        t1 += __shfl_xor_sync(0xffffffffu, t1, 1);
        t2 += __shfl_xor_sync(0xffffffffu, t2, 1);
        t3 += __shfl_xor_sync(0xffffffffu, t3, 1);
        t0 += __shfl_xor_sync(0xffffffffu, t0, 2);
        t1 += __shfl_xor_sync(0xffffffffu, t1, 2);
        t2 += __shfl_xor_sync(0xffffffffu, t2, 2);
        t3 += __shfl_xor_sync(0xffffffffu, t3, 2);

        float sc0 = t0 * 0.25f + eb0;
        float sc1 = t1 * 0.25f + eb1;
        float sc2 = t2 * 0.25f + eb2;
        float sc3 = t3 * 0.25f + eb3;

        float mx = fmaxf(fmaxf(sc0, sc1), fmaxf(sc2, sc3));
        float mn = fmaxf(m, mx);
        float scale = __expf(m - mn);
        float q0 = __expf(sc0 - mn);
        float q1 = __expf(sc1 - mn);
        float q2 = __expf(sc2 - mn);
        float q3 = __expf(sc3 - mn);
        d = d * scale + q0 + q1 + q2 + q3;
        acc.x = acc.x * scale + q0*v0.x + q1*v1.x + q2*v2.x + q3*v3.x;
        acc.y = acc.y * scale + q0*v0.y + q1*v1.y + q2*v2.y + q3*v3.y;
        acc.z = acc.z * scale + q0*v0.z + q1*v1.z + q2*v2.z + q3*v3.z;
        acc.w = acc.w * scale + q0*v0.w + q1*v1.w + q2*v2.w + q3*v3.w;
        m = mn;
    }

    for (; idx < e_; idx++) {
        int2 p = g_list2[idx];
        float4 kv = *reinterpret_cast<const float4*>(&qkv[(size_t)p.y * 384 + 128 + lane * 4]);
        float4 vv = *reinterpret_cast<const float4*>(&qkv[(size_t)p.y * 384 + 256 + lane * 4]);
        float eb = g_eb[(size_t)p.x * 8 + g];

        float s = qv.x*kv.x + qv.y*kv.y + qv.z*kv.z + qv.w*kv.w;
        s += __shfl_xor_sync(0xffffffffu, s, 1);
        s += __shfl_xor_sync(0xffffffffu, s, 2);
        s = s * 0.25f + eb;

        float mn = fmaxf(m, s);
        float scale = __expf(m - mn);
        float p_ = __expf(s - mn);
        d = d * scale + p_;
        acc.x = acc.x * scale + p_ * vv.x;
        acc.y = acc.y * scale + p_ * vv.y;
        acc.z = acc.z * scale + p_ * vv.z;
        acc.w = acc.w * scale + p_ * vv.w;
        m = mn;
    }

    sM[warp][lane] = m;
    sD[warp][lane] = d;
    sAcc[warp][lane] = acc;
    __syncthreads();

    if (half == 0 && valid) {
        float* op = &agg[(size_t)node * 128 + lane * 4];
        if (cnt == 0) {
            *reinterpret_cast<float4*>(op) = make_float4(0.f, 0.f, 0.f, 0.f);
        } else {
            float m1 = sM[warp + 1][lane];
            float d1 = sD[warp + 1][lane];
            float4 a1 = sAcc[warp + 1][lane];

            float mn = fmaxf(m, m1);
            float s0 = __expf(m - mn);
            float s1 = (m1 == NEG_INF) ? 0.f : __expf(m1 - mn);
            float dt = d * s0 + d1 * s1;
            float inv = 1.0f / dt;
            float4 o;
            o.x = (acc.x * s0 + a1.x * s1) * inv;
            o.y = (acc.y * s0 + a1.y * s1) * inv;
            o.z = (acc.z * s0 + a1.z * s1) * inv;
            o.w = (acc.w * s0 + a1.w * s1) * inv;
            *reinterpret_cast<float4*>(op) = o;
        }
    }
}

// ---------------- launch ----------------
extern "C" void kernel_launch(void* const* d_in, const int* in_sizes, int n_in,
                              void* d_out, int out_size)
{
    const float* x     = (const float*)d_in[0];
    const float* ea    = (const float*)d_in[1];
    const float* Wq    = (const float*)d_in[2];
    const float* bq    = (const float*)d_in[3];
    const float* Wk    = (const float*)d_in[4];
    const float* bk    = (const float*)d_in[5];
    const float* Wv    = (const float*)d_in[6];
    const float* bv    = (const float*)d_in[7];
    const float* We    = (const float*)d_in[8];
    const float* be    = (const float*)d_in[9];
    const float* Wo    = (const float*)d_in[10];
    const float* bo    = (const float*)d_in[11];
    const float* gamma = (const float*)d_in[12];
    const float* beta  = (const float*)d_in[13];
    const int*   ei    = (const int*)d_in[14];
    float* out = (float*)d_out;

    float *qkv, *agg;
    cudaGetSymbolAddress((void**)&qkv, g_qkv);
    cudaGetSymbolAddress((void**)&agg, g_agg);

    static bool attrSet = false;
    if (!attrSet) {
        cudaFuncSetAttribute(gemm_tf32_ln,
                             cudaFuncAttributeMaxDynamicSharedMemorySize, 69632);
        attrSet = true;
    }

    const size_t lnSmem = 128 * 132 * 4;

    // Split: part A = nodes [0, 25088) = 196 LN tiles; part B = rest (195 tiles).
    const int NA        = 25088;
    const int tilesA    = 196;                          // NA / 128
    const int tilesB    = 195;                          // covers rows [25088, 50048) clipped
    const int attnBlkA  = NA / 4;                       // 6272
    const int attnBlkB  = (NN - NA + 3) / 4;            // 6228

    cudaEventRecord(s_evFork, 0);
    cudaStreamWaitEvent(s_side,  s_evFork, 0);
    cudaStreamWaitEvent(s_side2, s_evFork, 0);

    // side stream 1: CSR
    zero_cnt_k<<<(NN + 255) / 256, 256, 0, s_side>>>();
    hist_k<<<(EE + 255) / 256, 256, 0, s_side>>>(ei);
    scan_k<<<1, 1024, 0, s_side>>>();
    scatter_k<<<(EE + 255) / 256, 256, 0, s_side>>>(ei);
    cudaEventRecord(s_evJoin, s_side);

    // side stream 2: edge bias
    ebias_k<<<(EE * 8 + 255) / 256, 256, 0, s_side2>>>(ea, We, be);
    cudaEventRecord(s_evJoin2, s_side2);

    // main stream: QKV GEMMs
    gemm_tf32<<<(NN + 127) / 128, 256>>>(x, Wq, bq, qkv, 384, 0);
    gemm_tf32<<<(NN + 127) / 128, 256>>>(x, Wk, bk, qkv, 384, 128);
    gemm_tf32<<<(NN + 127) / 128, 256>>>(x, Wv, bv, qkv, 384, 256);

    cudaStreamWaitEvent(0, s_evJoin, 0);
    cudaStreamWaitEvent(0, s_evJoin2, 0);

    // attn part A, then (overlapped) ln part A on side2 while attn part B runs on main
    attn_k<<<attnBlkA, 256>>>(qkv, agg, 0);
    cudaEventRecord(s_evA, 0);

    attn_k<<<attnBlkB, 256>>>(qkv, agg, NA);

    cudaStreamWaitEvent(s_side2, s_evA, 0);
    gemm_tf32_ln<<<tilesA, 256, lnSmem, s_side2>>>(agg, Wo, bo, gamma, beta, out, 0);
    cudaEventRecord(s_evLnA, s_side2);

    gemm_tf32_ln<<<tilesB, 256, lnSmem>>>(agg, Wo, bo, gamma, beta, out, tilesA);

    cudaStreamWaitEvent(0, s_evLnA, 0);
}

// round 9
// speedup vs baseline: 1.3431x; 1.0728x over previous
#include <cuda_runtime.h>
#include <cuda_fp16.h>
#include <math.h>

#define NN 50000
#define EE 800000

// ---------------- scratch ----------------
__device__ float  g_q  [NN * 128];     // q, fp32
__device__ __half g_kvh[NN * 256];     // per node: k halfs [0,128) | v halfs [128,256)
__device__ float  g_agg[NN * 128];
__device__ float  g_eb [EE * 8];       // per-(edge,head) bias: ea @ We + be
__device__ int    g_cnt[NN];
__device__ int    g_off[NN + 1];
__device__ int2   g_list2[EE];         // {edge id, src node} grouped by dst

// ---------------- streams/events ----------------
static cudaStream_t s_side, s_side2;
static cudaEvent_t  s_evFork, s_evJoin, s_evJoin2;
static struct StreamInit {
    StreamInit() {
        cudaStreamCreateWithFlags(&s_side,  cudaStreamNonBlocking);
        cudaStreamCreateWithFlags(&s_side2, cudaStreamNonBlocking);
        cudaEventCreateWithFlags(&s_evFork,  cudaEventDisableTiming);
        cudaEventCreateWithFlags(&s_evJoin,  cudaEventDisableTiming);
        cudaEventCreateWithFlags(&s_evJoin2, cudaEventDisableTiming);
    }
} s_streamInit;

// ---------------- CSR build ----------------
__global__ void zero_cnt_k() {
    int i = blockIdx.x * blockDim.x + threadIdx.x;
    if (i < NN) g_cnt[i] = 0;
}

__global__ void hist_k(const int* __restrict__ ei) {
    int e = blockIdx.x * blockDim.x + threadIdx.x;
    if (e < EE) atomicAdd(&g_cnt[ei[EE + e]], 1);
}

__global__ __launch_bounds__(1024) void scan_k() {
    __shared__ int ssum[1024];
    const int T = 1024;
    const int CH = (NN + T - 1) / T;
    int t = threadIdx.x;
    int base = t * CH;

    int loc = 0;
    for (int i = 0; i < CH; i++) {
        int idx = base + i;
        if (idx < NN) loc += g_cnt[idx];
    }
    ssum[t] = loc;
    __syncthreads();
    for (int o = 1; o < T; o <<= 1) {
        int v = (t >= o) ? ssum[t - o] : 0;
        __syncthreads();
        ssum[t] += v;
        __syncthreads();
    }
    int run = (t == 0) ? 0 : ssum[t - 1];
    for (int i = 0; i < CH; i++) {
        int idx = base + i;
        if (idx < NN) {
            int c = g_cnt[idx];
            g_off[idx] = run;
            g_cnt[idx] = 0;
            run += c;
        }
    }
    if (t == T - 1) g_off[NN] = run;
}

__global__ void scatter_k(const int* __restrict__ ei) {
    int e = blockIdx.x * blockDim.x + threadIdx.x;
    if (e < EE) {
        int src = ei[e];
        int dst = ei[EE + e];
        int pos = atomicAdd(&g_cnt[dst], 1);
        g_list2[g_off[dst] + pos] = make_int2(e, src);
    }
}

// ---------------- edge-bias precompute ----------------
__global__ __launch_bounds__(256) void ebias_k(
    const float* __restrict__ ea, const float* __restrict__ We,
    const float* __restrict__ be)
{
    __shared__ float sWe[256];
    __shared__ float sbe[8];
    int t = threadIdx.x;
    sWe[t] = We[t];
    if (t < 8) sbe[t] = be[t];
    __syncthreads();

    int gid = blockIdx.x * 256 + t;
    if (gid >= EE * 8) return;
    int e = gid >> 3, h = gid & 7;

    float s = sbe[h];
    const float4* ep = reinterpret_cast<const float4*>(ea + (size_t)e * 32);
#pragma unroll
    for (int i = 0; i < 8; i++) {
        float4 v = ep[i];
        s += v.x * sWe[(i * 4 + 0) * 8 + h] + v.y * sWe[(i * 4 + 1) * 8 + h]
           + v.z * sWe[(i * 4 + 2) * 8 + h] + v.w * sWe[(i * 4 + 3) * 8 + h];
    }
    g_eb[gid] = s;
}

// ---------------- TF32 helpers ----------------
__device__ __forceinline__ unsigned f2tf32(float f) {
    unsigned u;
    asm("cvt.rna.tf32.f32 %0, %1;" : "=r"(u) : "f"(f));
    return u;
}

__device__ __forceinline__ void mma_tf32(
    float& c0, float& c1, float& c2, float& c3,
    unsigned a0, unsigned a1, unsigned a2, unsigned a3,
    unsigned b0, unsigned b1)
{
    asm volatile(
        "mma.sync.aligned.m16n8k8.row.col.f32.tf32.tf32.f32 "
        "{%0,%1,%2,%3}, {%4,%5,%6,%7}, {%8,%9}, {%0,%1,%2,%3};"
        : "+f"(c0), "+f"(c1), "+f"(c2), "+f"(c3)
        : "r"(a0), "r"(a1), "r"(a2), "r"(a3), "r"(b0), "r"(b1));
}

#define BK 16

// ---------------- TF32 GEMM: fp32 out (q) OR fp16 out (k/v into g_kvh) ----------
__global__ __launch_bounds__(256) void gemm_qkvh(
    const float* __restrict__ A, const float* __restrict__ W,
    const float* __restrict__ bias,
    float* __restrict__ Cf,        // fp32 out (q) or null
    __half* __restrict__ Ch,       // fp16 out (k/v) or null
    int hoff)                      // half-column offset (0 for k, 128 for v)
{
    __shared__ unsigned As[2][BK][136];
    __shared__ unsigned Bs[2][BK][128];

    const int t    = threadIdx.x;
    const int wid  = t >> 5;
    const int lane = t & 31;
    const int wm   = wid & 1;
    const int wn   = wid >> 1;
    const int tig  = lane & 3;
    const int grp  = lane >> 2;
    const int rowBase = blockIdx.x * 128;

    float acc[4][4][4];
#pragma unroll
    for (int mi = 0; mi < 4; mi++)
#pragma unroll
        for (int ni = 0; ni < 4; ni++)
#pragma unroll
            for (int r = 0; r < 4; r++) acc[mi][ni][r] = 0.f;

    const int aRow0 = t >> 2;
    const int aC0   = (t & 3) << 2;
    const int aRow1 = (t + 256) >> 2;
    const int bK0 = t >> 5;
    const int bN0 = (t & 31) << 2;
    const int bK1 = bK0 + 8;

    const bool aOk0 = rowBase + aRow0 < NN;
    const bool aOk1 = rowBase + aRow1 < NN;
    const float* aP0 = A + (size_t)(rowBase + aRow0) * 128 + aC0;
    const float* aP1 = A + (size_t)(rowBase + aRow1) * 128 + aC0;

    float4 fa0 = make_float4(0.f,0.f,0.f,0.f), fa1 = fa0, fb0, fb1;
    if (aOk0) fa0 = *reinterpret_cast<const float4*>(aP0);
    if (aOk1) fa1 = *reinterpret_cast<const float4*>(aP1);
    fb0 = *reinterpret_cast<const float4*>(W + (size_t)bK0 * 128 + bN0);
    fb1 = *reinterpret_cast<const float4*>(W + (size_t)bK1 * 128 + bN0);

    int buf = 0;
    {
        As[0][aC0+0][aRow0] = f2tf32(fa0.x); As[0][aC0+1][aRow0] = f2tf32(fa0.y);
        As[0][aC0+2][aRow0] = f2tf32(fa0.z); As[0][aC0+3][aRow0] = f2tf32(fa0.w);
        As[0][aC0+0][aRow1] = f2tf32(fa1.x); As[0][aC0+1][aRow1] = f2tf32(fa1.y);
        As[0][aC0+2][aRow1] = f2tf32(fa1.z); As[0][aC0+3][aRow1] = f2tf32(fa1.w);
        Bs[0][bK0][bN0+0] = f2tf32(fb0.x); Bs[0][bK0][bN0+1] = f2tf32(fb0.y);
        Bs[0][bK0][bN0+2] = f2tf32(fb0.z); Bs[0][bK0][bN0+3] = f2tf32(fb0.w);
        Bs[0][bK1][bN0+0] = f2tf32(fb1.x); Bs[0][bK1][bN0+1] = f2tf32(fb1.y);
        Bs[0][bK1][bN0+2] = f2tf32(fb1.z); Bs[0][bK1][bN0+3] = f2tf32(fb1.w);
    }
    __syncthreads();

    for (int kb = 0; kb < 8; kb++) {
        const int nk = (kb + 1) * BK;
        if (kb < 7) {
            fa0 = make_float4(0.f,0.f,0.f,0.f); fa1 = fa0;
            if (aOk0) fa0 = *reinterpret_cast<const float4*>(aP0 + nk);
            if (aOk1) fa1 = *reinterpret_cast<const float4*>(aP1 + nk);
            fb0 = *reinterpret_cast<const float4*>(W + (size_t)(nk + bK0) * 128 + bN0);
            fb1 = *reinterpret_cast<const float4*>(W + (size_t)(nk + bK1) * 128 + bN0);
        }

#pragma unroll
        for (int ks = 0; ks < 2; ks++) {
            const int k0 = ks * 8;
            unsigned a[4][4];
#pragma unroll
            for (int mi = 0; mi < 4; mi++) {
                int mr = wm * 64 + mi * 16 + grp;
                a[mi][0] = As[buf][k0 + tig][mr];
                a[mi][1] = As[buf][k0 + tig][mr + 8];
                a[mi][2] = As[buf][k0 + tig + 4][mr];
                a[mi][3] = As[buf][k0 + tig + 4][mr + 8];
            }
            unsigned b[4][2];
#pragma unroll
            for (int ni = 0; ni < 4; ni++) {
                int nc = wn * 32 + ni * 8 + grp;
                b[ni][0] = Bs[buf][k0 + tig][nc];
                b[ni][1] = Bs[buf][k0 + tig + 4][nc];
            }
#pragma unroll
            for (int mi = 0; mi < 4; mi++)
#pragma unroll
                for (int ni = 0; ni < 4; ni++)
                    mma_tf32(acc[mi][ni][0], acc[mi][ni][1], acc[mi][ni][2], acc[mi][ni][3],
                             a[mi][0], a[mi][1], a[mi][2], a[mi][3],
                             b[ni][0], b[ni][1]);
        }

        if (kb < 7) {
            int nb = buf ^ 1;
            As[nb][aC0+0][aRow0] = f2tf32(fa0.x); As[nb][aC0+1][aRow0] = f2tf32(fa0.y);
            As[nb][aC0+2][aRow0] = f2tf32(fa0.z); As[nb][aC0+3][aRow0] = f2tf32(fa0.w);
            As[nb][aC0+0][aRow1] = f2tf32(fa1.x); As[nb][aC0+1][aRow1] = f2tf32(fa1.y);
            As[nb][aC0+2][aRow1] = f2tf32(fa1.z); As[nb][aC0+3][aRow1] = f2tf32(fa1.w);
            Bs[nb][bK0][bN0+0] = f2tf32(fb0.x); Bs[nb][bK0][bN0+1] = f2tf32(fb0.y);
            Bs[nb][bK0][bN0+2] = f2tf32(fb0.z); Bs[nb][bK0][bN0+3] = f2tf32(fb0.w);
            Bs[nb][bK1][bN0+0] = f2tf32(fb1.x); Bs[nb][bK1][bN0+1] = f2tf32(fb1.y);
            Bs[nb][bK1][bN0+2] = f2tf32(fb1.z); Bs[nb][bK1][bN0+3] = f2tf32(fb1.w);
            __syncthreads();
            buf = nb;
        }
    }

#pragma unroll
    for (int mi = 0; mi < 4; mi++) {
        int r0 = rowBase + wm * 64 + mi * 16 + grp;
        int r1 = r0 + 8;
#pragma unroll
        for (int ni = 0; ni < 4; ni++) {
            int c = wn * 32 + ni * 8 + tig * 2;
            float b0 = bias[c], b1 = bias[c + 1];
            float o00 = acc[mi][ni][0] + b0, o01 = acc[mi][ni][1] + b1;
            float o10 = acc[mi][ni][2] + b0, o11 = acc[mi][ni][3] + b1;
            if (Cf) {
                if (r0 < NN)
                    *reinterpret_cast<float2*>(Cf + (size_t)r0 * 128 + c) = make_float2(o00, o01);
                if (r1 < NN)
                    *reinterpret_cast<float2*>(Cf + (size_t)r1 * 128 + c) = make_float2(o10, o11);
            } else {
                if (r0 < NN)
                    *reinterpret_cast<__half2*>(Ch + (size_t)r0 * 256 + hoff + c) = __floats2half2_rn(o00, o01);
                if (r1 < NN)
                    *reinterpret_cast<__half2*>(Ch + (size_t)r1 * 256 + hoff + c) = __floats2half2_rn(o10, o11);
            }
        }
    }
}

// ---------------- TF32 GEMM + fused LayerNorm (Wo variant) ----------
__global__ __launch_bounds__(256) void gemm_tf32_ln(
    const float* __restrict__ A, const float* __restrict__ W,
    const float* __restrict__ bias,
    const float* __restrict__ gamma, const float* __restrict__ beta,
    float* __restrict__ out)
{
    extern __shared__ char sm_[];
    typedef unsigned AsT[BK][136];
    typedef unsigned BsT[BK][128];
    AsT* As = reinterpret_cast<AsT*>(sm_);
    BsT* Bs = reinterpret_cast<BsT*>(sm_ + 17408);
    float (*Ct)[132] = reinterpret_cast<float(*)[132]>(sm_);

    const int t    = threadIdx.x;
    const int wid  = t >> 5;
    const int lane = t & 31;
    const int wm   = wid & 1;
    const int wn   = wid >> 1;
    const int tig  = lane & 3;
    const int grp  = lane >> 2;
    const int rowBase = blockIdx.x * 128;

    float acc[4][4][4];
#pragma unroll
    for (int mi = 0; mi < 4; mi++)
#pragma unroll
        for (int ni = 0; ni < 4; ni++)
#pragma unroll
            for (int r = 0; r < 4; r++) acc[mi][ni][r] = 0.f;

    const int aRow0 = t >> 2;
    const int aC0   = (t & 3) << 2;
    const int aRow1 = (t + 256) >> 2;
    const int bK0 = t >> 5;
    const int bN0 = (t & 31) << 2;
    const int bK1 = bK0 + 8;

    const bool aOk0 = rowBase + aRow0 < NN;
    const bool aOk1 = rowBase + aRow1 < NN;
    const float* aP0 = A + (size_t)(rowBase + aRow0) * 128 + aC0;
    const float* aP1 = A + (size_t)(rowBase + aRow1) * 128 + aC0;

    float4 fa0 = make_float4(0.f,0.f,0.f,0.f), fa1 = fa0, fb0, fb1;
    if (aOk0) fa0 = *reinterpret_cast<const float4*>(aP0);
    if (aOk1) fa1 = *reinterpret_cast<const float4*>(aP1);
    fb0 = *reinterpret_cast<const float4*>(W + (size_t)bK0 * 128 + bN0);
    fb1 = *reinterpret_cast<const float4*>(W + (size_t)bK1 * 128 + bN0);

    int buf = 0;
    {
        As[0][aC0+0][aRow0] = f2tf32(fa0.x); As[0][aC0+1][aRow0] = f2tf32(fa0.y);
        As[0][aC0+2][aRow0] = f2tf32(fa0.z); As[0][aC0+3][aRow0] = f2tf32(fa0.w);
        As[0][aC0+0][aRow1] = f2tf32(fa1.x); As[0][aC0+1][aRow1] = f2tf32(fa1.y);
        As[0][aC0+2][aRow1] = f2tf32(fa1.z); As[0][aC0+3][aRow1] = f2tf32(fa1.w);
        Bs[0][bK0][bN0+0] = f2tf32(fb0.x); Bs[0][bK0][bN0+1] = f2tf32(fb0.y);
        Bs[0][bK0][bN0+2] = f2tf32(fb0.z); Bs[0][bK0][bN0+3] = f2tf32(fb0.w);
        Bs[0][bK1][bN0+0] = f2tf32(fb1.x); Bs[0][bK1][bN0+1] = f2tf32(fb1.y);
        Bs[0][bK1][bN0+2] = f2tf32(fb1.z); Bs[0][bK1][bN0+3] = f2tf32(fb1.w);
    }
    __syncthreads();

    for (int kb = 0; kb < 8; kb++) {
        const int nk = (kb + 1) * BK;
        if (kb < 7) {
            fa0 = make_float4(0.f,0.f,0.f,0.f); fa1 = fa0;
            if (aOk0) fa0 = *reinterpret_cast<const float4*>(aP0 + nk);
            if (aOk1) fa1 = *reinterpret_cast<const float4*>(aP1 + nk);
            fb0 = *reinterpret_cast<const float4*>(W + (size_t)(nk + bK0) * 128 + bN0);
            fb1 = *reinterpret_cast<const float4*>(W + (size_t)(nk + bK1) * 128 + bN0);
        }

#pragma unroll
        for (int ks = 0; ks < 2; ks++) {
            const int k0 = ks * 8;
            unsigned a[4][4];
#pragma unroll
            for (int mi = 0; mi < 4; mi++) {
                int mr = wm * 64 + mi * 16 + grp;
                a[mi][0] = As[buf][k0 + tig][mr];
                a[mi][1] = As[buf][k0 + tig][mr + 8];
                a[mi][2] = As[buf][k0 + tig + 4][mr];
                a[mi][3] = As[buf][k0 + tig + 4][mr + 8];
            }
            unsigned b[4][2];
#pragma unroll
            for (int ni = 0; ni < 4; ni++) {
                int nc = wn * 32 + ni * 8 + grp;
                b[ni][0] = Bs[buf][k0 + tig][nc];
                b[ni][1] = Bs[buf][k0 + tig + 4][nc];
            }
#pragma unroll
            for (int mi = 0; mi < 4; mi++)
#pragma unroll
                for (int ni = 0; ni < 4; ni++)
                    mma_tf32(acc[mi][ni][0], acc[mi][ni][1], acc[mi][ni][2], acc[mi][ni][3],
                             a[mi][0], a[mi][1], a[mi][2], a[mi][3],
                             b[ni][0], b[ni][1]);
        }

        if (kb < 7) {
            int nb = buf ^ 1;
            As[nb][aC0+0][aRow0] = f2tf32(fa0.x); As[nb][aC0+1][aRow0] = f2tf32(fa0.y);
            As[nb][aC0+2][aRow0] = f2tf32(fa0.z); As[nb][aC0+3][aRow0] = f2tf32(fa0.w);
            As[nb][aC0+0][aRow1] = f2tf32(fa1.x); As[nb][aC0+1][aRow1] = f2tf32(fa1.y);
            As[nb][aC0+2][aRow1] = f2tf32(fa1.z); As[nb][aC0+3][aRow1] = f2tf32(fa1.w);
            Bs[nb][bK0][bN0+0] = f2tf32(fb0.x); Bs[nb][bK0][bN0+1] = f2tf32(fb0.y);
            Bs[nb][bK0][bN0+2] = f2tf32(fb0.z); Bs[nb][bK0][bN0+3] = f2tf32(fb0.w);
            Bs[nb][bK1][bN0+0] = f2tf32(fb1.x); Bs[nb][bK1][bN0+1] = f2tf32(fb1.y);
            Bs[nb][bK1][bN0+2] = f2tf32(fb1.z); Bs[nb][bK1][bN0+3] = f2tf32(fb1.w);
            __syncthreads();
            buf = nb;
        }
    }

    __syncthreads();
#pragma unroll
    for (int mi = 0; mi < 4; mi++) {
        int lr0 = wm * 64 + mi * 16 + grp;
        int lr1 = lr0 + 8;
#pragma unroll
        for (int ni = 0; ni < 4; ni++) {
            int c = wn * 32 + ni * 8 + tig * 2;
            float b0 = bias[c], b1 = bias[c + 1];
            Ct[lr0][c]     = acc[mi][ni][0] + b0;
            Ct[lr0][c + 1] = acc[mi][ni][1] + b1;
            Ct[lr1][c]     = acc[mi][ni][2] + b0;
            Ct[lr1][c + 1] = acc[mi][ni][3] + b1;
        }
    }
    __syncthreads();

    {
        int r = t >> 1;
        int half = (t & 1) << 6;
        int grow = rowBase + r;
        if (grow < NN) {
            float s = 0.f;
#pragma unroll
            for (int i = 0; i < 64; i += 4) {
                float4 v = *reinterpret_cast<float4*>(&Ct[r][half + i]);
                s += v.x + v.y + v.z + v.w;
            }
            s += __shfl_xor_sync(0xffffffffu, s, 1);
            float mean = s * (1.0f / 128.0f);

            float s2 = 0.f;
#pragma unroll
            for (int i = 0; i < 64; i += 4) {
                float4 v = *reinterpret_cast<float4*>(&Ct[r][half + i]);
                float dx = v.x - mean, dy = v.y - mean, dz = v.z - mean, dw = v.w - mean;
                s2 += dx * dx + dy * dy + dz * dz + dw * dw;
            }
            s2 += __shfl_xor_sync(0xffffffffu, s2, 1);
            float rstd = rsqrtf(s2 * (1.0f / 128.0f) + 1e-5f);

            float* op = out + (size_t)grow * 128 + half;
#pragma unroll
            for (int i = 0; i < 64; i += 4) {
                float4 v = *reinterpret_cast<float4*>(&Ct[r][half + i]);
                float4 gm = *reinterpret_cast<const float4*>(gamma + half + i);
                float4 bt = *reinterpret_cast<const float4*>(beta + half + i);
                float4 o;
                o.x = (v.x - mean) * rstd * gm.x + bt.x;
                o.y = (v.y - mean) * rstd * gm.y + bt.y;
                o.z = (v.z - mean) * rstd * gm.z + bt.z;
                o.w = (v.w - mean) * rstd * gm.w + bt.w;
                *reinterpret_cast<float4*>(op + i) = o;
            }
        } else {
            float s = 0.f;
            s += __shfl_xor_sync(0xffffffffu, s, 1);
            float s2 = 0.f;
            s2 += __shfl_xor_sync(0xffffffffu, s2, 1);
            (void)s; (void)s2;
        }
    }
}

// ---------------- fused attention: 2 warps/node, chunk-4, fp16 k/v gathers ----------------
__device__ __forceinline__ void kv_expand(unsigned lo, unsigned hi, float4& f) {
    __half2 h0 = *reinterpret_cast<__half2*>(&lo);
    __half2 h1 = *reinterpret_cast<__half2*>(&hi);
    float2 a = __half22float2(h0);
    float2 b = __half22float2(h1);
    f = make_float4(a.x, a.y, b.x, b.y);
}

__global__ __launch_bounds__(256) void attn_k(
    const float* __restrict__ q, const __half* __restrict__ kvh,
    float* __restrict__ agg)
{
    __shared__ float4 sAcc[8][32];
    __shared__ float  sM[8][33];
    __shared__ float  sD[8][33];

    const int warp = threadIdx.x >> 5;
    const int lane = threadIdx.x & 31;
    const int slot = warp >> 1;
    const int half = warp & 1;
    const int node = blockIdx.x * 4 + slot;
    const bool valid = node < NN;

    const int g = lane >> 2;

    int beg = 0, end = 0;
    if (valid) { beg = g_off[node]; end = g_off[node + 1]; }
    const int cnt = end - beg;
    const int h0 = (cnt + 1) >> 1;
    const int b  = half ? (beg + h0) : beg;
    const int e_ = half ? end : (beg + h0);

    float4 qv = make_float4(0.f, 0.f, 0.f, 0.f);
    if (valid && cnt > 0)
        qv = *reinterpret_cast<const float4*>(&q[(size_t)node * 128 + lane * 4]);

    const float NEG_INF = -__int_as_float(0x7F800000);
    float m = NEG_INF;
    float d = 0.f;
    float4 acc = make_float4(0.f, 0.f, 0.f, 0.f);

    int idx = b;
    for (; idx + 3 < e_; idx += 4) {
        int2 p0 = g_list2[idx];
        int2 p1 = g_list2[idx + 1];
        int2 p2 = g_list2[idx + 2];
        int2 p3 = g_list2[idx + 3];

        // all gathers issued up front: 4x k(8B), 4x v(8B), 4x eb
        uint2 kr0 = *reinterpret_cast<const uint2*>(&kvh[(size_t)p0.y * 256 + lane * 4]);
        uint2 kr1 = *reinterpret_cast<const uint2*>(&kvh[(size_t)p1.y * 256 + lane * 4]);
        uint2 kr2 = *reinterpret_cast<const uint2*>(&kvh[(size_t)p2.y * 256 + lane * 4]);
        uint2 kr3 = *reinterpret_cast<const uint2*>(&kvh[(size_t)p3.y * 256 + lane * 4]);
        uint2 vr0 = *reinterpret_cast<const uint2*>(&kvh[(size_t)p0.y * 256 + 128 + lane * 4]);
        uint2 vr1 = *reinterpret_cast<const uint2*>(&kvh[(size_t)p1.y * 256 + 128 + lane * 4]);
        uint2 vr2 = *reinterpret_cast<const uint2*>(&kvh[(size_t)p2.y * 256 + 128 + lane * 4]);
        uint2 vr3 = *reinterpret_cast<const uint2*>(&kvh[(size_t)p3.y * 256 + 128 + lane * 4]);
        float eb0 = g_eb[(size_t)p0.x * 8 + g];
        float eb1 = g_eb[(size_t)p1.x * 8 + g];
        float eb2 = g_eb[(size_t)p2.x * 8 + g];
        float eb3 = g_eb[(size_t)p3.x * 8 + g];

        float4 k0, k1, k2, k3, v0, v1, v2, v3;
        kv_expand(kr0.x, kr0.y, k0);
        kv_expand(kr1.x, kr1.y, k1);
        kv_expand(kr2.x, kr2.y, k2);
        kv_expand(kr3.x, kr3.y, k3);
        kv_expand(vr0.x, vr0.y, v0);
        kv_expand(vr1.x, vr1.y, v1);
        kv_expand(vr2.x, vr2.y, v2);
        kv_expand(vr3.x, vr3.y, v3);

        float t0 = qv.x*k0.x + qv.y*k0.y + qv.z*k0.z + qv.w*k0.w;
        float t1 = qv.x*k1.x + qv.y*k1.y + qv.z*k1.z + qv.w*k1.w;
        float t2 = qv.x*k2.x + qv.y*k2.y + qv.z*k2.z + qv.w*k2.w;
        float t3 = qv.x*k3.x + qv.y*k3.y + qv.z*k3.z + qv.w*k3.w;

        t0 += __shfl_xor_sync(0xffffffffu, t0, 1);
        t1 += __shfl_xor_sync(0xffffffffu, t1, 1);
        t2 += __shfl_xor_sync(0xffffffffu, t2, 1);
        t3 += __shfl_xor_sync(0xffffffffu, t3, 1);
        t0 += __shfl_xor_sync(0xffffffffu, t0, 2);
        t1 += __shfl_xor_sync(0xffffffffu, t1, 2);
        t2 += __shfl_xor_sync(0xffffffffu, t2, 2);
        t3 += __shfl_xor_sync(0xffffffffu, t3, 2);

        float sc0 = t0 * 0.25f + eb0;
        float sc1 = t1 * 0.25f + eb1;
        float sc2 = t2 * 0.25f + eb2;
        float sc3 = t3 * 0.25f + eb3;

        float mx = fmaxf(fmaxf(sc0, sc1), fmaxf(sc2, sc3));
        float mn = fmaxf(m, mx);
        float scale = __expf(m - mn);
        float q0 = __expf(sc0 - mn);
        float q1 = __expf(sc1 - mn);
        float q2 = __expf(sc2 - mn);
        float q3 = __expf(sc3 - mn);
        d = d * scale + q0 + q1 + q2 + q3;
        acc.x = acc.x * scale + q0*v0.x + q1*v1.x + q2*v2.x + q3*v3.x;
        acc.y = acc.y * scale + q0*v0.y + q1*v1.y + q2*v2.y + q3*v3.y;
        acc.z = acc.z * scale + q0*v0.z + q1*v1.z + q2*v2.z + q3*v3.z;
        acc.w = acc.w * scale + q0*v0.w + q1*v1.w + q2*v2.w + q3*v3.w;
        m = mn;
    }

    for (; idx < e_; idx++) {
        int2 p = g_list2[idx];
        uint2 kr = *reinterpret_cast<const uint2*>(&kvh[(size_t)p.y * 256 + lane * 4]);
        uint2 vr = *reinterpret_cast<const uint2*>(&kvh[(size_t)p.y * 256 + 128 + lane * 4]);
        float eb = g_eb[(size_t)p.x * 8 + g];
        float4 kv, vv;
        kv_expand(kr.x, kr.y, kv);
        kv_expand(vr.x, vr.y, vv);

        float s = qv.x*kv.x + qv.y*kv.y + qv.z*kv.z + qv.w*kv.w;
        s += __shfl_xor_sync(0xffffffffu, s, 1);
        s += __shfl_xor_sync(0xffffffffu, s, 2);
        s = s * 0.25f + eb;

        float mn = fmaxf(m, s);
        float scale = __expf(m - mn);
        float p_ = __expf(s - mn);
        d = d * scale + p_;
        acc.x = acc.x * scale + p_ * vv.x;
        acc.y = acc.y * scale + p_ * vv.y;
        acc.z = acc.z * scale + p_ * vv.z;
        acc.w = acc.w * scale + p_ * vv.w;
        m = mn;
    }

    sM[warp][lane] = m;
    sD[warp][lane] = d;
    sAcc[warp][lane] = acc;
    __syncthreads();

    if (half == 0 && valid) {
        float* op = &agg[(size_t)node * 128 + lane * 4];
        if (cnt == 0) {
            *reinterpret_cast<float4*>(op) = make_float4(0.f, 0.f, 0.f, 0.f);
        } else {
            float m1 = sM[warp + 1][lane];
            float d1 = sD[warp + 1][lane];
            float4 a1 = sAcc[warp + 1][lane];

            float mn = fmaxf(m, m1);
            float s0 = __expf(m - mn);
            float s1 = (m1 == NEG_INF) ? 0.f : __expf(m1 - mn);
            float dt = d * s0 + d1 * s1;
            float inv = 1.0f / dt;
            float4 o;
            o.x = (acc.x * s0 + a1.x * s1) * inv;
            o.y = (acc.y * s0 + a1.y * s1) * inv;
            o.z = (acc.z * s0 + a1.z * s1) * inv;
            o.w = (acc.w * s0 + a1.w * s1) * inv;
            *reinterpret_cast<float4*>(op) = o;
        }
    }
}

// ---------------- launch ----------------
extern "C" void kernel_launch(void* const* d_in, const int* in_sizes, int n_in,
                              void* d_out, int out_size)
{
    const float* x     = (const float*)d_in[0];
    const float* ea    = (const float*)d_in[1];
    const float* Wq    = (const float*)d_in[2];
    const float* bq    = (const float*)d_in[3];
    const float* Wk    = (const float*)d_in[4];
    const float* bk    = (const float*)d_in[5];
    const float* Wv    = (const float*)d_in[6];
    const float* bv    = (const float*)d_in[7];
    const float* We    = (const float*)d_in[8];
    const float* be    = (const float*)d_in[9];
    const float* Wo    = (const float*)d_in[10];
    const float* bo    = (const float*)d_in[11];
    const float* gamma = (const float*)d_in[12];
    const float* beta  = (const float*)d_in[13];
    const int*   ei    = (const int*)d_in[14];
    float* out = (float*)d_out;

    float *qp, *agg;
    __half *kvh;
    cudaGetSymbolAddress((void**)&qp,  g_q);
    cudaGetSymbolAddress((void**)&kvh, g_kvh);
    cudaGetSymbolAddress((void**)&agg, g_agg);

    static bool attrSet = false;
    if (!attrSet) {
        cudaFuncSetAttribute(gemm_tf32_ln,
                             cudaFuncAttributeMaxDynamicSharedMemorySize, 69632);
        attrSet = true;
    }

    const int nTiles = (NN + 127) / 128;
    const size_t lnSmem = 128 * 132 * 4;

    cudaEventRecord(s_evFork, 0);
    cudaStreamWaitEvent(s_side,  s_evFork, 0);
    cudaStreamWaitEvent(s_side2, s_evFork, 0);

    // side stream 1: CSR
    zero_cnt_k<<<(NN + 255) / 256, 256, 0, s_side>>>();
    hist_k<<<(EE + 255) / 256, 256, 0, s_side>>>(ei);
    scan_k<<<1, 1024, 0, s_side>>>();
    scatter_k<<<(EE + 255) / 256, 256, 0, s_side>>>(ei);
    cudaEventRecord(s_evJoin, s_side);

    // side stream 2: edge bias
    ebias_k<<<(EE * 8 + 255) / 256, 256, 0, s_side2>>>(ea, We, be);
    cudaEventRecord(s_evJoin2, s_side2);

    // main stream: QKV GEMMs (q fp32; k,v fp16 packed)
    gemm_qkvh<<<nTiles, 256>>>(x, Wq, bq, qp, nullptr, 0);
    gemm_qkvh<<<nTiles, 256>>>(x, Wk, bk, nullptr, kvh, 0);
    gemm_qkvh<<<nTiles, 256>>>(x, Wv, bv, nullptr, kvh, 128);

    cudaStreamWaitEvent(0, s_evJoin, 0);
    cudaStreamWaitEvent(0, s_evJoin2, 0);

    attn_k<<<(NN + 3) / 4, 256>>>(qp, kvh, agg);

    gemm_tf32_ln<<<nTiles, 256, lnSmem>>>(agg, Wo, bo, gamma, beta, out);
}

// round 10
// speedup vs baseline: 1.6251x; 1.2100x over previous
#include <cuda_runtime.h>
#include <cuda_fp16.h>
#include <math.h>

#define NN 50000
#define EE 800000

// ---------------- scratch ----------------
__device__ float  g_q  [NN * 128];     // q, fp32
__device__ __half g_kvh[NN * 256];     // per node: k halfs [0,128) | v halfs [128,256)
__device__ float  g_agg[NN * 128];
__device__ float  g_eb [EE * 8];       // per-(edge,head) bias: ea @ We + be
__device__ int    g_cnt[NN];
__device__ int    g_off[NN + 1];
__device__ int    g_bsum[256];         // per-block sums for parallel scan (196 used)
__device__ int2   g_list2[EE];         // {edge id, src node} grouped by dst

// ---------------- streams/events ----------------
static cudaStream_t s_side, s_side2;
static cudaEvent_t  s_evFork, s_evJoin, s_evJoin2;
static struct StreamInit {
    StreamInit() {
        cudaStreamCreateWithFlags(&s_side,  cudaStreamNonBlocking);
        cudaStreamCreateWithFlags(&s_side2, cudaStreamNonBlocking);
        cudaEventCreateWithFlags(&s_evFork,  cudaEventDisableTiming);
        cudaEventCreateWithFlags(&s_evJoin,  cudaEventDisableTiming);
        cudaEventCreateWithFlags(&s_evJoin2, cudaEventDisableTiming);
    }
} s_streamInit;

// ---------------- CSR build ----------------
__global__ void zero_cnt_k() {
    int i = blockIdx.x * blockDim.x + threadIdx.x;
    if (i < NN) g_cnt[i] = 0;
}

__global__ void hist_k(const int* __restrict__ ei) {
    int e = blockIdx.x * blockDim.x + threadIdx.x;
    if (e < EE) atomicAdd(&g_cnt[ei[EE + e]], 1);
}

// parallel scan stage 1: block-local inclusive scan (coalesced), write
// within-block EXCLUSIVE prefix to g_off, block total to g_bsum.
__global__ __launch_bounds__(256) void scan1_k() {
    __shared__ int sh[256];
    int t = threadIdx.x;
    int i = blockIdx.x * 256 + t;
    int c = (i < NN) ? g_cnt[i] : 0;
    sh[t] = c;
    __syncthreads();
#pragma unroll
    for (int o = 1; o < 256; o <<= 1) {
        int v = (t >= o) ? sh[t - o] : 0;
        __syncthreads();
        sh[t] += v;
        __syncthreads();
    }
    if (i < NN) g_off[i] = sh[t] - c;          // exclusive within block
    if (t == 255) g_bsum[blockIdx.x] = sh[255];
}

// stage 2: single small block scans the 196 block sums (exclusive, in place).
__global__ __launch_bounds__(256) void scan2_k(int nb) {
    __shared__ int sh[256];
    int t = threadIdx.x;
    int c = (t < nb) ? g_bsum[t] : 0;
    sh[t] = c;
    __syncthreads();
#pragma unroll
    for (int o = 1; o < 256; o <<= 1) {
        int v = (t >= o) ? sh[t - o] : 0;
        __syncthreads();
        sh[t] += v;
        __syncthreads();
    }
    if (t < nb) g_bsum[t] = sh[t] - c;         // exclusive block prefix
    if (t == 0) g_off[NN] = EE;                // total is constant
}

// stage 3: add block prefix, zero cnt (cursor reuse for scatter).
__global__ __launch_bounds__(256) void scan3_k() {
    int i = blockIdx.x * 256 + threadIdx.x;
    if (i < NN) {
        g_off[i] += g_bsum[blockIdx.x];
        g_cnt[i] = 0;
    }
}

__global__ void scatter_k(const int* __restrict__ ei) {
    int e = blockIdx.x * blockDim.x + threadIdx.x;
    if (e < EE) {
        int src = ei[e];
        int dst = ei[EE + e];
        int pos = atomicAdd(&g_cnt[dst], 1);
        g_list2[g_off[dst] + pos] = make_int2(e, src);
    }
}

// ---------------- edge-bias precompute ----------------
__global__ __launch_bounds__(256) void ebias_k(
    const float* __restrict__ ea, const float* __restrict__ We,
    const float* __restrict__ be)
{
    __shared__ float sWe[256];
    __shared__ float sbe[8];
    int t = threadIdx.x;
    sWe[t] = We[t];
    if (t < 8) sbe[t] = be[t];
    __syncthreads();

    int gid = blockIdx.x * 256 + t;
    if (gid >= EE * 8) return;
    int e = gid >> 3, h = gid & 7;

    float s = sbe[h];
    const float4* ep = reinterpret_cast<const float4*>(ea + (size_t)e * 32);
#pragma unroll
    for (int i = 0; i < 8; i++) {
        float4 v = ep[i];
        s += v.x * sWe[(i * 4 + 0) * 8 + h] + v.y * sWe[(i * 4 + 1) * 8 + h]
           + v.z * sWe[(i * 4 + 2) * 8 + h] + v.w * sWe[(i * 4 + 3) * 8 + h];
    }
    g_eb[gid] = s;
}

// ---------------- TF32 helpers ----------------
__device__ __forceinline__ unsigned f2tf32(float f) {
    unsigned u;
    asm("cvt.rna.tf32.f32 %0, %1;" : "=r"(u) : "f"(f));
    return u;
}

__device__ __forceinline__ void mma_tf32(
    float& c0, float& c1, float& c2, float& c3,
    unsigned a0, unsigned a1, unsigned a2, unsigned a3,
    unsigned b0, unsigned b1)
{
    asm volatile(
        "mma.sync.aligned.m16n8k8.row.col.f32.tf32.tf32.f32 "
        "{%0,%1,%2,%3}, {%4,%5,%6,%7}, {%8,%9}, {%0,%1,%2,%3};"
        : "+f"(c0), "+f"(c1), "+f"(c2), "+f"(c3)
        : "r"(a0), "r"(a1), "r"(a2), "r"(a3), "r"(b0), "r"(b1));
}

#define BK 16

// ---------------- TF32 GEMM: fp32 out (q) OR fp16 out (k/v into g_kvh) ----------
__global__ __launch_bounds__(256) void gemm_qkvh(
    const float* __restrict__ A, const float* __restrict__ W,
    const float* __restrict__ bias,
    float* __restrict__ Cf,        // fp32 out (q) or null
    __half* __restrict__ Ch,       // fp16 out (k/v) or null
    int hoff)                      // half-column offset (0 for k, 128 for v)
{
    __shared__ unsigned As[2][BK][136];
    __shared__ unsigned Bs[2][BK][128];

    const int t    = threadIdx.x;
    const int wid  = t >> 5;
    const int lane = t & 31;
    const int wm   = wid & 1;
    const int wn   = wid >> 1;
    const int tig  = lane & 3;
    const int grp  = lane >> 2;
    const int rowBase = blockIdx.x * 128;

    float acc[4][4][4];
#pragma unroll
    for (int mi = 0; mi < 4; mi++)
#pragma unroll
        for (int ni = 0; ni < 4; ni++)
#pragma unroll
            for (int r = 0; r < 4; r++) acc[mi][ni][r] = 0.f;

    const int aRow0 = t >> 2;
    const int aC0   = (t & 3) << 2;
    const int aRow1 = (t + 256) >> 2;
    const int bK0 = t >> 5;
    const int bN0 = (t & 31) << 2;
    const int bK1 = bK0 + 8;

    const bool aOk0 = rowBase + aRow0 < NN;
    const bool aOk1 = rowBase + aRow1 < NN;
    const float* aP0 = A + (size_t)(rowBase + aRow0) * 128 + aC0;
    const float* aP1 = A + (size_t)(rowBase + aRow1) * 128 + aC0;

    float4 fa0 = make_float4(0.f,0.f,0.f,0.f), fa1 = fa0, fb0, fb1;
    if (aOk0) fa0 = *reinterpret_cast<const float4*>(aP0);
    if (aOk1) fa1 = *reinterpret_cast<const float4*>(aP1);
    fb0 = *reinterpret_cast<const float4*>(W + (size_t)bK0 * 128 + bN0);
    fb1 = *reinterpret_cast<const float4*>(W + (size_t)bK1 * 128 + bN0);

    int buf = 0;
    {
        As[0][aC0+0][aRow0] = f2tf32(fa0.x); As[0][aC0+1][aRow0] = f2tf32(fa0.y);
        As[0][aC0+2][aRow0] = f2tf32(fa0.z); As[0][aC0+3][aRow0] = f2tf32(fa0.w);
        As[0][aC0+0][aRow1] = f2tf32(fa1.x); As[0][aC0+1][aRow1] = f2tf32(fa1.y);
        As[0][aC0+2][aRow1] = f2tf32(fa1.z); As[0][aC0+3][aRow1] = f2tf32(fa1.w);
        Bs[0][bK0][bN0+0] = f2tf32(fb0.x); Bs[0][bK0][bN0+1] = f2tf32(fb0.y);
        Bs[0][bK0][bN0+2] = f2tf32(fb0.z); Bs[0][bK0][bN0+3] = f2tf32(fb0.w);
        Bs[0][bK1][bN0+0] = f2tf32(fb1.x); Bs[0][bK1][bN0+1] = f2tf32(fb1.y);
        Bs[0][bK1][bN0+2] = f2tf32(fb1.z); Bs[0][bK1][bN0+3] = f2tf32(fb1.w);
    }
    __syncthreads();

    for (int kb = 0; kb < 8; kb++) {
        const int nk = (kb + 1) * BK;
        if (kb < 7) {
            fa0 = make_float4(0.f,0.f,0.f,0.f); fa1 = fa0;
            if (aOk0) fa0 = *reinterpret_cast<const float4*>(aP0 + nk);
            if (aOk1) fa1 = *reinterpret_cast<const float4*>(aP1 + nk);
            fb0 = *reinterpret_cast<const float4*>(W + (size_t)(nk + bK0) * 128 + bN0);
            fb1 = *reinterpret_cast<const float4*>(W + (size_t)(nk + bK1) * 128 + bN0);
        }

#pragma unroll
        for (int ks = 0; ks < 2; ks++) {
            const int k0 = ks * 8;
            unsigned a[4][4];
#pragma unroll
            for (int mi = 0; mi < 4; mi++) {
                int mr = wm * 64 + mi * 16 + grp;
                a[mi][0] = As[buf][k0 + tig][mr];
                a[mi][1] = As[buf][k0 + tig][mr + 8];
                a[mi][2] = As[buf][k0 + tig + 4][mr];
                a[mi][3] = As[buf][k0 + tig + 4][mr + 8];
            }
            unsigned b[4][2];
#pragma unroll
            for (int ni = 0; ni < 4; ni++) {
                int nc = wn * 32 + ni * 8 + grp;
                b[ni][0] = Bs[buf][k0 + tig][nc];
                b[ni][1] = Bs[buf][k0 + tig + 4][nc];
            }
#pragma unroll
            for (int mi = 0; mi < 4; mi++)
#pragma unroll
                for (int ni = 0; ni < 4; ni++)
                    mma_tf32(acc[mi][ni][0], acc[mi][ni][1], acc[mi][ni][2], acc[mi][ni][3],
                             a[mi][0], a[mi][1], a[mi][2], a[mi][3],
                             b[ni][0], b[ni][1]);
        }

        if (kb < 7) {
            int nb = buf ^ 1;
            As[nb][aC0+0][aRow0] = f2tf32(fa0.x); As[nb][aC0+1][aRow0] = f2tf32(fa0.y);
            As[nb][aC0+2][aRow0] = f2tf32(fa0.z); As[nb][aC0+3][aRow0] = f2tf32(fa0.w);
            As[nb][aC0+0][aRow1] = f2tf32(fa1.x); As[nb][aC0+1][aRow1] = f2tf32(fa1.y);
            As[nb][aC0+2][aRow1] = f2tf32(fa1.z); As[nb][aC0+3][aRow1] = f2tf32(fa1.w);
            Bs[nb][bK0][bN0+0] = f2tf32(fb0.x); Bs[nb][bK0][bN0+1] = f2tf32(fb0.y);
            Bs[nb][bK0][bN0+2] = f2tf32(fb0.z); Bs[nb][bK0][bN0+3] = f2tf32(fb0.w);
            Bs[nb][bK1][bN0+0] = f2tf32(fb1.x); Bs[nb][bK1][bN0+1] = f2tf32(fb1.y);
            Bs[nb][bK1][bN0+2] = f2tf32(fb1.z); Bs[nb][bK1][bN0+3] = f2tf32(fb1.w);
            __syncthreads();
            buf = nb;
        }
    }

#pragma unroll
    for (int mi = 0; mi < 4; mi++) {
        int r0 = rowBase + wm * 64 + mi * 16 + grp;
        int r1 = r0 + 8;
#pragma unroll
        for (int ni = 0; ni < 4; ni++) {
            int c = wn * 32 + ni * 8 + tig * 2;
            float b0 = bias[c], b1 = bias[c + 1];
            float o00 = acc[mi][ni][0] + b0, o01 = acc[mi][ni][1] + b1;
            float o10 = acc[mi][ni][2] + b0, o11 = acc[mi][ni][3] + b1;
            if (Cf) {
                if (r0 < NN)
                    *reinterpret_cast<float2*>(Cf + (size_t)r0 * 128 + c) = make_float2(o00, o01);
                if (r1 < NN)
                    *reinterpret_cast<float2*>(Cf + (size_t)r1 * 128 + c) = make_float2(o10, o11);
            } else {
                if (r0 < NN)
                    *reinterpret_cast<__half2*>(Ch + (size_t)r0 * 256 + hoff + c) = __floats2half2_rn(o00, o01);
                if (r1 < NN)
                    *reinterpret_cast<__half2*>(Ch + (size_t)r1 * 256 + hoff + c) = __floats2half2_rn(o10, o11);
            }
        }
    }
}

// ---------------- TF32 GEMM + fused LayerNorm (Wo variant) ----------
__global__ __launch_bounds__(256) void gemm_tf32_ln(
    const float* __restrict__ A, const float* __restrict__ W,
    const float* __restrict__ bias,
    const float* __restrict__ gamma, const float* __restrict__ beta,
    float* __restrict__ out)
{
    extern __shared__ char sm_[];
    typedef unsigned AsT[BK][136];
    typedef unsigned BsT[BK][128];
    AsT* As = reinterpret_cast<AsT*>(sm_);
    BsT* Bs = reinterpret_cast<BsT*>(sm_ + 17408);
    float (*Ct)[132] = reinterpret_cast<float(*)[132]>(sm_);

    const int t    = threadIdx.x;
    const int wid  = t >> 5;
    const int lane = t & 31;
    const int wm   = wid & 1;
    const int wn   = wid >> 1;
    const int tig  = lane & 3;
    const int grp  = lane >> 2;
    const int rowBase = blockIdx.x * 128;

    float acc[4][4][4];
#pragma unroll
    for (int mi = 0; mi < 4; mi++)
#pragma unroll
        for (int ni = 0; ni < 4; ni++)
#pragma unroll
            for (int r = 0; r < 4; r++) acc[mi][ni][r] = 0.f;

    const int aRow0 = t >> 2;
    const int aC0   = (t & 3) << 2;
    const int aRow1 = (t + 256) >> 2;
    const int bK0 = t >> 5;
    const int bN0 = (t & 31) << 2;
    const int bK1 = bK0 + 8;

    const bool aOk0 = rowBase + aRow0 < NN;
    const bool aOk1 = rowBase + aRow1 < NN;
    const float* aP0 = A + (size_t)(rowBase + aRow0) * 128 + aC0;
    const float* aP1 = A + (size_t)(rowBase + aRow1) * 128 + aC0;

    float4 fa0 = make_float4(0.f,0.f,0.f,0.f), fa1 = fa0, fb0, fb1;
    if (aOk0) fa0 = *reinterpret_cast<const float4*>(aP0);
    if (aOk1) fa1 = *reinterpret_cast<const float4*>(aP1);
    fb0 = *reinterpret_cast<const float4*>(W + (size_t)bK0 * 128 + bN0);
    fb1 = *reinterpret_cast<const float4*>(W + (size_t)bK1 * 128 + bN0);

    int buf = 0;
    {
        As[0][aC0+0][aRow0] = f2tf32(fa0.x); As[0][aC0+1][aRow0] = f2tf32(fa0.y);
        As[0][aC0+2][aRow0] = f2tf32(fa0.z); As[0][aC0+3][aRow0] = f2tf32(fa0.w);
        As[0][aC0+0][aRow1] = f2tf32(fa1.x); As[0][aC0+1][aRow1] = f2tf32(fa1.y);
        As[0][aC0+2][aRow1] = f2tf32(fa1.z); As[0][aC0+3][aRow1] = f2tf32(fa1.w);
        Bs[0][bK0][bN0+0] = f2tf32(fb0.x); Bs[0][bK0][bN0+1] = f2tf32(fb0.y);
        Bs[0][bK0][bN0+2] = f2tf32(fb0.z); Bs[0][bK0][bN0+3] = f2tf32(fb0.w);
        Bs[0][bK1][bN0+0] = f2tf32(fb1.x); Bs[0][bK1][bN0+1] = f2tf32(fb1.y);
        Bs[0][bK1][bN0+2] = f2tf32(fb1.z); Bs[0][bK1][bN0+3] = f2tf32(fb1.w);
    }
    __syncthreads();

    for (int kb = 0; kb < 8; kb++) {
        const int nk = (kb + 1) * BK;
        if (kb < 7) {
            fa0 = make_float4(0.f,0.f,0.f,0.f); fa1 = fa0;
            if (aOk0) fa0 = *reinterpret_cast<const float4*>(aP0 + nk);
            if (aOk1) fa1 = *reinterpret_cast<const float4*>(aP1 + nk);
            fb0 = *reinterpret_cast<const float4*>(W + (size_t)(nk + bK0) * 128 + bN0);
            fb1 = *reinterpret_cast<const float4*>(W + (size_t)(nk + bK1) * 128 + bN0);
        }

#pragma unroll
        for (int ks = 0; ks < 2; ks++) {
            const int k0 = ks * 8;
            unsigned a[4][4];
#pragma unroll
            for (int mi = 0; mi < 4; mi++) {
                int mr = wm * 64 + mi * 16 + grp;
                a[mi][0] = As[buf][k0 + tig][mr];
                a[mi][1] = As[buf][k0 + tig][mr + 8];
                a[mi][2] = As[buf][k0 + tig + 4][mr];
                a[mi][3] = As[buf][k0 + tig + 4][mr + 8];
            }
            unsigned b[4][2];
#pragma unroll
            for (int ni = 0; ni < 4; ni++) {
                int nc = wn * 32 + ni * 8 + grp;
                b[ni][0] = Bs[buf][k0 + tig][nc];
                b[ni][1] = Bs[buf][k0 + tig + 4][nc];
            }
#pragma unroll
            for (int mi = 0; mi < 4; mi++)
#pragma unroll
                for (int ni = 0; ni < 4; ni++)
                    mma_tf32(acc[mi][ni][0], acc[mi][ni][1], acc[mi][ni][2], acc[mi][ni][3],
                             a[mi][0], a[mi][1], a[mi][2], a[mi][3],
                             b[ni][0], b[ni][1]);
        }

        if (kb < 7) {
            int nb = buf ^ 1;
            As[nb][aC0+0][aRow0] = f2tf32(fa0.x); As[nb][aC0+1][aRow0] = f2tf32(fa0.y);
            As[nb][aC0+2][aRow0] = f2tf32(fa0.z); As[nb][aC0+3][aRow0] = f2tf32(fa0.w);
            As[nb][aC0+0][aRow1] = f2tf32(fa1.x); As[nb][aC0+1][aRow1] = f2tf32(fa1.y);
            As[nb][aC0+2][aRow1] = f2tf32(fa1.z); As[nb][aC0+3][aRow1] = f2tf32(fa1.w);
            Bs[nb][bK0][bN0+0] = f2tf32(fb0.x); Bs[nb][bK0][bN0+1] = f2tf32(fb0.y);
            Bs[nb][bK0][bN0+2] = f2tf32(fb0.z); Bs[nb][bK0][bN0+3] = f2tf32(fb0.w);
            Bs[nb][bK1][bN0+0] = f2tf32(fb1.x); Bs[nb][bK1][bN0+1] = f2tf32(fb1.y);
            Bs[nb][bK1][bN0+2] = f2tf32(fb1.z); Bs[nb][bK1][bN0+3] = f2tf32(fb1.w);
            __syncthreads();
            buf = nb;
        }
    }

    __syncthreads();
#pragma unroll
    for (int mi = 0; mi < 4; mi++) {
        int lr0 = wm * 64 + mi * 16 + grp;
        int lr1 = lr0 + 8;
#pragma unroll
        for (int ni = 0; ni < 4; ni++) {
            int c = wn * 32 + ni * 8 + tig * 2;
            float b0 = bias[c], b1 = bias[c + 1];
            Ct[lr0][c]     = acc[mi][ni][0] + b0;
            Ct[lr0][c + 1] = acc[mi][ni][1] + b1;
            Ct[lr1][c]     = acc[mi][ni][2] + b0;
            Ct[lr1][c + 1] = acc[mi][ni][3] + b1;
        }
    }
    __syncthreads();

    {
        int r = t >> 1;
        int half = (t & 1) << 6;
        int grow = rowBase + r;
        if (grow < NN) {
            float s = 0.f;
#pragma unroll
            for (int i = 0; i < 64; i += 4) {
                float4 v = *reinterpret_cast<float4*>(&Ct[r][half + i]);
                s += v.x + v.y + v.z + v.w;
            }
            s += __shfl_xor_sync(0xffffffffu, s, 1);
            float mean = s * (1.0f / 128.0f);

            float s2 = 0.f;
#pragma unroll
            for (int i = 0; i < 64; i += 4) {
                float4 v = *reinterpret_cast<float4*>(&Ct[r][half + i]);
                float dx = v.x - mean, dy = v.y - mean, dz = v.z - mean, dw = v.w - mean;
                s2 += dx * dx + dy * dy + dz * dz + dw * dw;
            }
            s2 += __shfl_xor_sync(0xffffffffu, s2, 1);
            float rstd = rsqrtf(s2 * (1.0f / 128.0f) + 1e-5f);

            float* op = out + (size_t)grow * 128 + half;
#pragma unroll
            for (int i = 0; i < 64; i += 4) {
                float4 v = *reinterpret_cast<float4*>(&Ct[r][half + i]);
                float4 gm = *reinterpret_cast<const float4*>(gamma + half + i);
                float4 bt = *reinterpret_cast<const float4*>(beta + half + i);
                float4 o;
                o.x = (v.x - mean) * rstd * gm.x + bt.x;
                o.y = (v.y - mean) * rstd * gm.y + bt.y;
                o.z = (v.z - mean) * rstd * gm.z + bt.z;
                o.w = (v.w - mean) * rstd * gm.w + bt.w;
                *reinterpret_cast<float4*>(op + i) = o;
            }
        } else {
            float s = 0.f;
            s += __shfl_xor_sync(0xffffffffu, s, 1);
            float s2 = 0.f;
            s2 += __shfl_xor_sync(0xffffffffu, s2, 1);
            (void)s; (void)s2;
        }
    }
}

// ---------------- fused attention: 2 warps/node, chunk-4, fp16 k/v gathers ----------------
__device__ __forceinline__ void kv_expand(unsigned lo, unsigned hi, float4& f) {
    __half2 h0 = *reinterpret_cast<__half2*>(&lo);
    __half2 h1 = *reinterpret_cast<__half2*>(&hi);
    float2 a = __half22float2(h0);
    float2 b = __half22float2(h1);
    f = make_float4(a.x, a.y, b.x, b.y);
}

__global__ __launch_bounds__(256) void attn_k(
    const float* __restrict__ q, const __half* __restrict__ kvh,
    float* __restrict__ agg)
{
    __shared__ float4 sAcc[8][32];
    __shared__ float  sM[8][33];
    __shared__ float  sD[8][33];

    const int warp = threadIdx.x >> 5;
    const int lane = threadIdx.x & 31;
    const int slot = warp >> 1;
    const int half = warp & 1;
    const int node = blockIdx.x * 4 + slot;
    const bool valid = node < NN;

    const int g = lane >> 2;

    int beg = 0, end = 0;
    if (valid) { beg = g_off[node]; end = g_off[node + 1]; }
    const int cnt = end - beg;
    const int h0 = (cnt + 1) >> 1;
    const int b  = half ? (beg + h0) : beg;
    const int e_ = half ? end : (beg + h0);

    float4 qv = make_float4(0.f, 0.f, 0.f, 0.f);
    if (valid && cnt > 0)
        qv = *reinterpret_cast<const float4*>(&q[(size_t)node * 128 + lane * 4]);

    const float NEG_INF = -__int_as_float(0x7F800000);
    float m = NEG_INF;
    float d = 0.f;
    float4 acc = make_float4(0.f, 0.f, 0.f, 0.f);

    int idx = b;
    for (; idx + 3 < e_; idx += 4) {
        int2 p0 = g_list2[idx];
        int2 p1 = g_list2[idx + 1];
        int2 p2 = g_list2[idx + 2];
        int2 p3 = g_list2[idx + 3];

        uint2 kr0 = *reinterpret_cast<const uint2*>(&kvh[(size_t)p0.y * 256 + lane * 4]);
        uint2 kr1 = *reinterpret_cast<const uint2*>(&kvh[(size_t)p1.y * 256 + lane * 4]);
        uint2 kr2 = *reinterpret_cast<const uint2*>(&kvh[(size_t)p2.y * 256 + lane * 4]);
        uint2 kr3 = *reinterpret_cast<const uint2*>(&kvh[(size_t)p3.y * 256 + lane * 4]);
        uint2 vr0 = *reinterpret_cast<const uint2*>(&kvh[(size_t)p0.y * 256 + 128 + lane * 4]);
        uint2 vr1 = *reinterpret_cast<const uint2*>(&kvh[(size_t)p1.y * 256 + 128 + lane * 4]);
        uint2 vr2 = *reinterpret_cast<const uint2*>(&kvh[(size_t)p2.y * 256 + 128 + lane * 4]);
        uint2 vr3 = *reinterpret_cast<const uint2*>(&kvh[(size_t)p3.y * 256 + 128 + lane * 4]);
        float eb0 = g_eb[(size_t)p0.x * 8 + g];
        float eb1 = g_eb[(size_t)p1.x * 8 + g];
        float eb2 = g_eb[(size_t)p2.x * 8 + g];
        float eb3 = g_eb[(size_t)p3.x * 8 + g];

        float4 k0, k1, k2, k3, v0, v1, v2, v3;
        kv_expand(kr0.x, kr0.y, k0);
        kv_expand(kr1.x, kr1.y, k1);
        kv_expand(kr2.x, kr2.y, k2);
        kv_expand(kr3.x, kr3.y, k3);
        kv_expand(vr0.x, vr0.y, v0);
        kv_expand(vr1.x, vr1.y, v1);
        kv_expand(vr2.x, vr2.y, v2);
        kv_expand(vr3.x, vr3.y, v3);

        float t0 = qv.x*k0.x + qv.y*k0.y + qv.z*k0.z + qv.w*k0.w;
        float t1 = qv.x*k1.x + qv.y*k1.y + qv.z*k1.z + qv.w*k1.w;
        float t2 = qv.x*k2.x + qv.y*k2.y + qv.z*k2.z + qv.w*k2.w;
        float t3 = qv.x*k3.x + qv.y*k3.y + qv.z*k3.z + qv.w*k3.w;

        t0 += __shfl_xor_sync(0xffffffffu, t0, 1);
        t1 += __shfl_xor_sync(0xffffffffu, t1, 1);
        t2 += __shfl_xor_sync(0xffffffffu, t2, 1);
        t3 += __shfl_xor_sync(0xffffffffu, t3, 1);
        t0 += __shfl_xor_sync(0xffffffffu, t0, 2);
        t1 += __shfl_xor_sync(0xffffffffu, t1, 2);
        t2 += __shfl_xor_sync(0xffffffffu, t2, 2);
        t3 += __shfl_xor_sync(0xffffffffu, t3, 2);

        float sc0 = t0 * 0.25f + eb0;
        float sc1 = t1 * 0.25f + eb1;
        float sc2 = t2 * 0.25f + eb2;
        float sc3 = t3 * 0.25f + eb3;

        float mx = fmaxf(fmaxf(sc0, sc1), fmaxf(sc2, sc3));
        float mn = fmaxf(m, mx);
        float scale = __expf(m - mn);
        float q0 = __expf(sc0 - mn);
        float q1 = __expf(sc1 - mn);
        float q2 = __expf(sc2 - mn);
        float q3 = __expf(sc3 - mn);
        d = d * scale + q0 + q1 + q2 + q3;
        acc.x = acc.x * scale + q0*v0.x + q1*v1.x + q2*v2.x + q3*v3.x;
        acc.y = acc.y * scale + q0*v0.y + q1*v1.y + q2*v2.y + q3*v3.y;
        acc.z = acc.z * scale + q0*v0.z + q1*v1.z + q2*v2.z + q3*v3.z;
        acc.w = acc.w * scale + q0*v0.w + q1*v1.w + q2*v2.w + q3*v3.w;
        m = mn;
    }

    for (; idx < e_; idx++) {
        int2 p = g_list2[idx];
        uint2 kr = *reinterpret_cast<const uint2*>(&kvh[(size_t)p.y * 256 + lane * 4]);
        uint2 vr = *reinterpret_cast<const uint2*>(&kvh[(size_t)p.y * 256 + 128 + lane * 4]);
        float eb = g_eb[(size_t)p.x * 8 + g];
        float4 kv, vv;
        kv_expand(kr.x, kr.y, kv);
        kv_expand(vr.x, vr.y, vv);

        float s = qv.x*kv.x + qv.y*kv.y + qv.z*kv.z + qv.w*kv.w;
        s += __shfl_xor_sync(0xffffffffu, s, 1);
        s += __shfl_xor_sync(0xffffffffu, s, 2);
        s = s * 0.25f + eb;

        float mn = fmaxf(m, s);
        float scale = __expf(m - mn);
        float p_ = __expf(s - mn);
        d = d * scale + p_;
        acc.x = acc.x * scale + p_ * vv.x;
        acc.y = acc.y * scale + p_ * vv.y;
        acc.z = acc.z * scale + p_ * vv.z;
        acc.w = acc.w * scale + p_ * vv.w;
        m = mn;
    }

    sM[warp][lane] = m;
    sD[warp][lane] = d;
    sAcc[warp][lane] = acc;
    __syncthreads();

    if (half == 0 && valid) {
        float* op = &agg[(size_t)node * 128 + lane * 4];
        if (cnt == 0) {
            *reinterpret_cast<float4*>(op) = make_float4(0.f, 0.f, 0.f, 0.f);
        } else {
            float m1 = sM[warp + 1][lane];
            float d1 = sD[warp + 1][lane];
            float4 a1 = sAcc[warp + 1][lane];

            float mn = fmaxf(m, m1);
            float s0 = __expf(m - mn);
            float s1 = (m1 == NEG_INF) ? 0.f : __expf(m1 - mn);
            float dt = d * s0 + d1 * s1;
            float inv = 1.0f / dt;
            float4 o;
            o.x = (acc.x * s0 + a1.x * s1) * inv;
            o.y = (acc.y * s0 + a1.y * s1) * inv;
            o.z = (acc.z * s0 + a1.z * s1) * inv;
            o.w = (acc.w * s0 + a1.w * s1) * inv;
            *reinterpret_cast<float4*>(op) = o;
        }
    }
}

// ---------------- launch ----------------
extern "C" void kernel_launch(void* const* d_in, const int* in_sizes, int n_in,
                              void* d_out, int out_size)
{
    const float* x     = (const float*)d_in[0];
    const float* ea    = (const float*)d_in[1];
    const float* Wq    = (const float*)d_in[2];
    const float* bq    = (const float*)d_in[3];
    const float* Wk    = (const float*)d_in[4];
    const float* bk    = (const float*)d_in[5];
    const float* Wv    = (const float*)d_in[6];
    const float* bv    = (const float*)d_in[7];
    const float* We    = (const float*)d_in[8];
    const float* be    = (const float*)d_in[9];
    const float* Wo    = (const float*)d_in[10];
    const float* bo    = (const float*)d_in[11];
    const float* gamma = (const float*)d_in[12];
    const float* beta  = (const float*)d_in[13];
    const int*   ei    = (const int*)d_in[14];
    float* out = (float*)d_out;

    float *qp, *agg;
    __half *kvh;
    cudaGetSymbolAddress((void**)&qp,  g_q);
    cudaGetSymbolAddress((void**)&kvh, g_kvh);
    cudaGetSymbolAddress((void**)&agg, g_agg);

    static bool attrSet = false;
    if (!attrSet) {
        cudaFuncSetAttribute(gemm_tf32_ln,
                             cudaFuncAttributeMaxDynamicSharedMemorySize, 69632);
        attrSet = true;
    }

    const int nTiles  = (NN + 127) / 128;
    const int nScanB  = (NN + 255) / 256;   // 196
    const size_t lnSmem = 128 * 132 * 4;

    cudaEventRecord(s_evFork, 0);
    cudaStreamWaitEvent(s_side,  s_evFork, 0);
    cudaStreamWaitEvent(s_side2, s_evFork, 0);

    // side stream 1: CSR (parallel 3-stage scan)
    zero_cnt_k<<<nScanB, 256, 0, s_side>>>();
    hist_k<<<(EE + 255) / 256, 256, 0, s_side>>>(ei);
    scan1_k<<<nScanB, 256, 0, s_side>>>();
    scan2_k<<<1, 256, 0, s_side>>>(nScanB);
    scan3_k<<<nScanB, 256, 0, s_side>>>();
    scatter_k<<<(EE + 255) / 256, 256, 0, s_side>>>(ei);
    cudaEventRecord(s_evJoin, s_side);

    // side stream 2: edge bias
    ebias_k<<<(EE * 8 + 255) / 256, 256, 0, s_side2>>>(ea, We, be);
    cudaEventRecord(s_evJoin2, s_side2);

    // main stream: QKV GEMMs (q fp32; k,v fp16 packed)
    gemm_qkvh<<<nTiles, 256>>>(x, Wq, bq, qp, nullptr, 0);
    gemm_qkvh<<<nTiles, 256>>>(x, Wk, bk, nullptr, kvh, 0);
    gemm_qkvh<<<nTiles, 256>>>(x, Wv, bv, nullptr, kvh, 128);

    cudaStreamWaitEvent(0, s_evJoin, 0);
    cudaStreamWaitEvent(0, s_evJoin2, 0);

    attn_k<<<(NN + 3) / 4, 256>>>(qp, kvh, agg);

    gemm_tf32_ln<<<nTiles, 256, lnSmem>>>(agg, Wo, bo, gamma, beta, out);
}